// round 9
// baseline (speedup 1.0000x reference)
#include <cuda_runtime.h>
#include <math.h>
#include <stdint.h>

#define N_ENT 1024
#define BATCH 128
#define T_TOK 64
#define P_TOK 49
#define D_IN 768
#define H_DIM 512
#define N_EXP 8

// ----------------------------- static scratch ------------------------------
__device__ float g_etc[N_ENT * H_DIM];
__device__ float g_eic[N_ENT * H_DIM];
__device__ float g_mtc[BATCH * H_DIM];
__device__ float g_mic[BATCH * H_DIM];
__device__ float g_ett[N_ENT * T_TOK * H_DIM];
__device__ float g_eit[N_ENT * P_TOK * H_DIM];
__device__ float g_mtt[BATCH * T_TOK * H_DIM];
__device__ float g_mit[BATCH * P_TOK * H_DIM];

__device__ float g_eti_m[N_ENT * 50 * H_DIM];
__device__ float g_mti_m[BATCH * 50 * H_DIM];
__device__ float g_eit_m[N_ENT * 65 * H_DIM];
__device__ float g_mit_m[BATCH * 65 * H_DIM];

__device__ int2   g_eidx[4][N_ENT];
__device__ float2 g_ew[4][N_ENT];

__device__ float g_ctx0[N_ENT * H_DIM];
__device__ float g_ctx1[BATCH * H_DIM];
__device__ float g_ctx2[N_ENT * H_DIM];
__device__ float g_ctx3[BATCH * H_DIM];

__device__ float g_fe_ti[N_ENT * H_DIM];
__device__ float g_fm_ti[BATCH * H_DIM];
__device__ float g_fe_it[N_ENT * H_DIM];
__device__ float g_fm_it[BATCH * H_DIM];

__device__ float g_wc_text[D_IN * N_EXP];
__device__ float g_wc_img[D_IN * N_EXP];
__device__ float g_bterm[2 * N_EXP];

// ------------------------------ tf32 helpers -------------------------------
__device__ __forceinline__ void split_tf32(float x, uint32_t& hi, uint32_t& lo)
{
    asm("cvt.rna.tf32.f32 %0, %1;" : "=r"(hi) : "f"(x));
    float r = x - __uint_as_float(hi);
    asm("cvt.rna.tf32.f32 %0, %1;" : "=r"(lo) : "f"(r));
}

__device__ __forceinline__ void split4(float4 v, uint4& h, uint4& l)
{
    split_tf32(v.x, h.x, l.x); split_tf32(v.y, h.y, l.y);
    split_tf32(v.z, h.z, l.z); split_tf32(v.w, h.w, l.w);
}

__device__ __forceinline__ void mma8(float* c, const uint32_t* a, const uint32_t* b)
{
    asm volatile(
        "mma.sync.aligned.m16n8k8.row.col.f32.tf32.tf32.f32 "
        "{%0,%1,%2,%3}, {%4,%5,%6,%7}, {%8,%9}, {%0,%1,%2,%3};"
        : "+f"(c[0]), "+f"(c[1]), "+f"(c[2]), "+f"(c[3])
        : "r"(a[0]), "r"(a[1]), "r"(a[2]), "r"(a[3]), "r"(b[0]), "r"(b[1]));
}

#define ASTR 20    // 20*lane mod 32 distinct -> conflict-free A access
#define BSTR 136   // 136 mod 32 == 8 -> 8*tig+gid distinct (loads)
#define BSTR2 264  // 264 mod 32 == 8 -> same property, 256-col tiles

// ----------------- proj (3xTF32): C[M,512]=A[M,768]@W+bias -----------------
// 128 threads, block 128x128, 4 warps of 64x64, 2 CTAs/SM.
__global__ __launch_bounds__(128, 2) void proj_tc(
    const float* __restrict__ A, const float* __restrict__ W,
    const float* __restrict__ bias, float* __restrict__ C, int M)
{
    __shared__ uint32_t AsH[128 * ASTR], AsL[128 * ASTR];
    __shared__ uint32_t BsH[16 * BSTR], BsL[16 * BSTR];

    const int tid = threadIdx.x;
    const int row0 = blockIdx.x * 128;
    const int col0 = blockIdx.y * 128;
    const int warp = tid >> 5, lane = tid & 31;
    const int wm = warp >> 1, wn = warp & 1;
    const int gid = lane >> 2, tig = lane & 3;
    const int bk = tid >> 3, cg = tid & 7;

    float acc[4][8][4];
#pragma unroll
    for (int a = 0; a < 4; a++)
#pragma unroll
        for (int b = 0; b < 8; b++)
#pragma unroll
            for (int c = 0; c < 4; c++) acc[a][b][c] = 0.f;

    const float* Arow = A + (size_t)(row0 + tid) * D_IN;

    for (int kb = 0; kb < D_IN / 16; kb++) {
        const int k0 = kb * 16;
        // load + convert + store (transient regs; overlap via 2 CTAs/SM)
#pragma unroll
        for (int q = 0; q < 4; q++) {
            float4 va = *(const float4*)(Arow + k0 + q * 4);
            uint4 h, l;
            split4(va, h, l);
            int base = tid * ASTR + q * 4;
            *(uint4*)&AsH[base] = h; *(uint4*)&AsL[base] = l;
            float4 vb = *(const float4*)(W + (size_t)(k0 + bk) * H_DIM + col0 + cg * 4 + 32 * q);
            split4(vb, h, l);
            int bb = bk * BSTR + cg * 4 + 32 * q;
            *(uint4*)&BsH[bb] = h; *(uint4*)&BsL[bb] = l;
        }
        __syncthreads();
#pragma unroll
        for (int kk = 0; kk < 16; kk += 8) {
            uint32_t ah[4][4], al[4][4], bh[8][2], bl[8][2];
#pragma unroll
            for (int mt = 0; mt < 4; mt++) {
                int b0 = (wm * 64 + mt * 16 + gid) * ASTR + kk + tig;
                ah[mt][0] = AsH[b0];     ah[mt][1] = AsH[b0 + 8 * ASTR];
                ah[mt][2] = AsH[b0 + 4]; ah[mt][3] = AsH[b0 + 8 * ASTR + 4];
                al[mt][0] = AsL[b0];     al[mt][1] = AsL[b0 + 8 * ASTR];
                al[mt][2] = AsL[b0 + 4]; al[mt][3] = AsL[b0 + 8 * ASTR + 4];
            }
#pragma unroll
            for (int nt = 0; nt < 8; nt++) {
                int b0 = (kk + tig) * BSTR + wn * 64 + nt * 8 + gid;
                bh[nt][0] = BsH[b0]; bh[nt][1] = BsH[b0 + 4 * BSTR];
                bl[nt][0] = BsL[b0]; bl[nt][1] = BsL[b0 + 4 * BSTR];
            }
#pragma unroll
            for (int mt = 0; mt < 4; mt++)
#pragma unroll
                for (int nt = 0; nt < 8; nt++) mma8(acc[mt][nt], ah[mt], bh[nt]);
#pragma unroll
            for (int mt = 0; mt < 4; mt++)
#pragma unroll
                for (int nt = 0; nt < 8; nt++) mma8(acc[mt][nt], ah[mt], bl[nt]);
#pragma unroll
            for (int mt = 0; mt < 4; mt++)
#pragma unroll
                for (int nt = 0; nt < 8; nt++) mma8(acc[mt][nt], al[mt], bh[nt]);
        }
        __syncthreads();
    }

#pragma unroll
    for (int mt = 0; mt < 4; mt++) {
        int m = row0 + wm * 64 + mt * 16 + gid;
#pragma unroll
        for (int nt = 0; nt < 8; nt++) {
            int n = col0 + wn * 64 + nt * 8 + tig * 2;
            float2 bv = *(const float2*)(bias + n);
            *(float2*)(C + (size_t)m * H_DIM + n) =
                make_float2(acc[mt][nt][0] + bv.x, acc[mt][nt][1] + bv.y);
            *(float2*)(C + (size_t)(m + 8) * H_DIM + n) =
                make_float2(acc[mt][nt][2] + bv.x, acc[mt][nt][3] + bv.y);
        }
    }
}

// -------- MoE S=50 (3xTF32): block 64x256, 4 warps of 64x64, 2+ CTAs/SM ----
__global__ __launch_bounds__(128, 2) void moe2_tc(
    const float* __restrict__ cls, const float* __restrict__ tok,
    const float* __restrict__ We, const float* __restrict__ be,
    const int2* __restrict__ eidx, const float2* __restrict__ ew,
    float* __restrict__ out)
{
    const int S = 50;
    __shared__ uint32_t AsH[64 * ASTR], AsL[64 * ASTR];
    __shared__ uint32_t BsH[16 * BSTR2], BsL[16 * BSTR2];

    const int i = blockIdx.z;
    const int col0 = blockIdx.x * 256;
    const int2 e = eidx[i];
    const float2 w = ew[i];
    const float* W0 = We + (size_t)e.x * H_DIM * H_DIM;
    const float* W1 = We + (size_t)e.y * H_DIM * H_DIM;

    const int tid = threadIdx.x;
    const int warp = tid >> 5, lane = tid & 31;
    const int wn = warp;                 // 4 warps across N, all cover M=64
    const int gid = lane >> 2, tig = lane & 3;
    const int bk = tid >> 3, cg = tid & 7;
    const int arow = tid & 63, ahalf = tid >> 6;   // 2 threads per A row

    const float* rp = nullptr;
    if (arow < S)
        rp = (arow == 0) ? (cls + (size_t)i * H_DIM)
                         : (tok + ((size_t)i * (S - 1) + (arow - 1)) * H_DIM);

    float acc[4][8][4];
#pragma unroll
    for (int a = 0; a < 4; a++)
#pragma unroll
        for (int b = 0; b < 8; b++)
#pragma unroll
            for (int c = 0; c < 4; c++) acc[a][b][c] = 0.f;

    for (int kb = 0; kb < H_DIM / 16; kb++) {
        const int k0 = kb * 16;
#pragma unroll
        for (int q = 0; q < 2; q++) {
            float4 v = make_float4(0.f, 0.f, 0.f, 0.f);
            if (rp) v = *(const float4*)(rp + k0 + ahalf * 8 + q * 4);
            uint4 h, l;
            split4(v, h, l);
            int base = arow * ASTR + ahalf * 8 + q * 4;
            *(uint4*)&AsH[base] = h; *(uint4*)&AsL[base] = l;
        }
#pragma unroll
        for (int q = 0; q < 8; q++) {
            size_t off = (size_t)(k0 + bk) * H_DIM + col0 + cg * 4 + 32 * q;
            float4 v0 = *(const float4*)(W0 + off);
            float4 v1 = *(const float4*)(W1 + off);
            float4 v = make_float4(w.x * v0.x + w.y * v1.x, w.x * v0.y + w.y * v1.y,
                                   w.x * v0.z + w.y * v1.z, w.x * v0.w + w.y * v1.w);
            uint4 h, l;
            split4(v, h, l);
            int bb = bk * BSTR2 + cg * 4 + 32 * q;
            *(uint4*)&BsH[bb] = h; *(uint4*)&BsL[bb] = l;
        }
        __syncthreads();
#pragma unroll
        for (int kk = 0; kk < 16; kk += 8) {
            uint32_t ah[4][4], al[4][4], bh[8][2], bl[8][2];
#pragma unroll
            for (int mt = 0; mt < 4; mt++) {
                int b0 = (mt * 16 + gid) * ASTR + kk + tig;
                ah[mt][0] = AsH[b0];     ah[mt][1] = AsH[b0 + 8 * ASTR];
                ah[mt][2] = AsH[b0 + 4]; ah[mt][3] = AsH[b0 + 8 * ASTR + 4];
                al[mt][0] = AsL[b0];     al[mt][1] = AsL[b0 + 8 * ASTR];
                al[mt][2] = AsL[b0 + 4]; al[mt][3] = AsL[b0 + 8 * ASTR + 4];
            }
#pragma unroll
            for (int nt = 0; nt < 8; nt++) {
                int b0 = (kk + tig) * BSTR2 + wn * 64 + nt * 8 + gid;
                bh[nt][0] = BsH[b0]; bh[nt][1] = BsH[b0 + 4 * BSTR2];
                bl[nt][0] = BsL[b0]; bl[nt][1] = BsL[b0 + 4 * BSTR2];
            }
#pragma unroll
            for (int mt = 0; mt < 4; mt++)
#pragma unroll
                for (int nt = 0; nt < 8; nt++) mma8(acc[mt][nt], ah[mt], bh[nt]);
#pragma unroll
            for (int mt = 0; mt < 4; mt++)
#pragma unroll
                for (int nt = 0; nt < 8; nt++) mma8(acc[mt][nt], ah[mt], bl[nt]);
#pragma unroll
            for (int mt = 0; mt < 4; mt++)
#pragma unroll
                for (int nt = 0; nt < 8; nt++) mma8(acc[mt][nt], al[mt], bh[nt]);
        }
        __syncthreads();
    }

#pragma unroll
    for (int mt = 0; mt < 4; mt++) {
        int t = mt * 16 + gid;
#pragma unroll
        for (int nt = 0; nt < 8; nt++) {
            int n = col0 + wn * 64 + nt * 8 + tig * 2;
            float b0 = w.x * be[e.x * H_DIM + n]     + w.y * be[e.y * H_DIM + n];
            float b1 = w.x * be[e.x * H_DIM + n + 1] + w.y * be[e.y * H_DIM + n + 1];
            if (t < S)
                *(float2*)(out + ((size_t)i * S + t) * H_DIM + n) =
                    make_float2(acc[mt][nt][0] + b0, acc[mt][nt][1] + b1);
            if (t + 8 < S)
                *(float2*)(out + ((size_t)i * S + t + 8) * H_DIM + n) =
                    make_float2(acc[mt][nt][2] + b0, acc[mt][nt][3] + b1);
        }
    }
}

// -------- MoE S=65 (3xTF32): block 96x128, 4 warps of 48x64, 2 CTAs/SM -----
__global__ __launch_bounds__(128, 2) void moe3_tc(
    const float* __restrict__ cls, const float* __restrict__ tok,
    const float* __restrict__ We, const float* __restrict__ be,
    const int2* __restrict__ eidx, const float2* __restrict__ ew,
    float* __restrict__ out)
{
    const int S = 65;
    __shared__ uint32_t AsH[96 * ASTR], AsL[96 * ASTR];
    __shared__ uint32_t BsH[16 * BSTR], BsL[16 * BSTR];

    const int i = blockIdx.z;
    const int col0 = blockIdx.x * 128;
    const int2 e = eidx[i];
    const float2 w = ew[i];
    const float* W0 = We + (size_t)e.x * H_DIM * H_DIM;
    const float* W1 = We + (size_t)e.y * H_DIM * H_DIM;

    const int tid = threadIdx.x;
    const int warp = tid >> 5, lane = tid & 31;
    const int wm = warp >> 1, wn = warp & 1;
    const int gid = lane >> 2, tig = lane & 3;
    const int bk = tid >> 3, cg = tid & 7;

    const float* rp = nullptr;
    if (tid < S)
        rp = (tid == 0) ? (cls + (size_t)i * H_DIM)
                        : (tok + ((size_t)i * (S - 1) + (tid - 1)) * H_DIM);

    float acc[3][8][4];
#pragma unroll
    for (int a = 0; a < 3; a++)
#pragma unroll
        for (int b = 0; b < 8; b++)
#pragma unroll
            for (int c = 0; c < 4; c++) acc[a][b][c] = 0.f;

    for (int kb = 0; kb < H_DIM / 16; kb++) {
        const int k0 = kb * 16;
        if (tid < 96) {
#pragma unroll
            for (int q = 0; q < 4; q++) {
                float4 v = make_float4(0.f, 0.f, 0.f, 0.f);
                if (rp) v = *(const float4*)(rp + k0 + q * 4);
                uint4 h, l;
                split4(v, h, l);
                int base = tid * ASTR + q * 4;
                *(uint4*)&AsH[base] = h; *(uint4*)&AsL[base] = l;
            }
        }
#pragma unroll
        for (int q = 0; q < 4; q++) {
            size_t off = (size_t)(k0 + bk) * H_DIM + col0 + cg * 4 + 32 * q;
            float4 v0 = *(const float4*)(W0 + off);
            float4 v1 = *(const float4*)(W1 + off);
            float4 v = make_float4(w.x * v0.x + w.y * v1.x, w.x * v0.y + w.y * v1.y,
                                   w.x * v0.z + w.y * v1.z, w.x * v0.w + w.y * v1.w);
            uint4 h, l;
            split4(v, h, l);
            int bb = bk * BSTR + cg * 4 + 32 * q;
            *(uint4*)&BsH[bb] = h; *(uint4*)&BsL[bb] = l;
        }
        __syncthreads();
#pragma unroll
        for (int kk = 0; kk < 16; kk += 8) {
            uint32_t ah[3][4], al[3][4], bh[8][2], bl[8][2];
#pragma unroll
            for (int mt = 0; mt < 3; mt++) {
                int b0 = (wm * 48 + mt * 16 + gid) * ASTR + kk + tig;
                ah[mt][0] = AsH[b0];     ah[mt][1] = AsH[b0 + 8 * ASTR];
                ah[mt][2] = AsH[b0 + 4]; ah[mt][3] = AsH[b0 + 8 * ASTR + 4];
                al[mt][0] = AsL[b0];     al[mt][1] = AsL[b0 + 8 * ASTR];
                al[mt][2] = AsL[b0 + 4]; al[mt][3] = AsL[b0 + 8 * ASTR + 4];
            }
#pragma unroll
            for (int nt = 0; nt < 8; nt++) {
                int b0 = (kk + tig) * BSTR + wn * 64 + nt * 8 + gid;
                bh[nt][0] = BsH[b0]; bh[nt][1] = BsH[b0 + 4 * BSTR];
                bl[nt][0] = BsL[b0]; bl[nt][1] = BsL[b0 + 4 * BSTR];
            }
#pragma unroll
            for (int mt = 0; mt < 3; mt++)
#pragma unroll
                for (int nt = 0; nt < 8; nt++) mma8(acc[mt][nt], ah[mt], bh[nt]);
#pragma unroll
            for (int mt = 0; mt < 3; mt++)
#pragma unroll
                for (int nt = 0; nt < 8; nt++) mma8(acc[mt][nt], ah[mt], bl[nt]);
#pragma unroll
            for (int mt = 0; mt < 3; mt++)
#pragma unroll
                for (int nt = 0; nt < 8; nt++) mma8(acc[mt][nt], al[mt], bh[nt]);
        }
        __syncthreads();
    }

#pragma unroll
    for (int mt = 0; mt < 3; mt++) {
        int t = wm * 48 + mt * 16 + gid;
#pragma unroll
        for (int nt = 0; nt < 8; nt++) {
            int n = col0 + wn * 64 + nt * 8 + tig * 2;
            float b0 = w.x * be[e.x * H_DIM + n]     + w.y * be[e.y * H_DIM + n];
            float b1 = w.x * be[e.x * H_DIM + n + 1] + w.y * be[e.y * H_DIM + n + 1];
            if (t < S)
                *(float2*)(out + ((size_t)i * S + t) * H_DIM + n) =
                    make_float2(acc[mt][nt][0] + b0, acc[mt][nt][1] + b1);
            if (t + 8 < S)
                *(float2*)(out + ((size_t)i * S + t + 8) * H_DIM + n) =
                    make_float2(acc[mt][nt][2] + b0, acc[mt][nt][3] + b1);
        }
    }
}

// --------------------- router weight folding (fp32-exact) ------------------
__global__ void combine_w_kernel(const float* __restrict__ Wt, const float* __restrict__ Wi,
                                 const float* __restrict__ Wr,
                                 float* __restrict__ WcT, float* __restrict__ WcI)
{
    int idx = blockIdx.x * blockDim.x + threadIdx.x;
    if (idx >= D_IN * N_EXP) return;
    int k = idx >> 3, e = idx & 7;
    float st = 0.f, si = 0.f;
    for (int h = 0; h < H_DIM; h++) {
        float wr = Wr[h * N_EXP + e];
        st += Wt[(size_t)k * H_DIM + h] * wr;
        si += Wi[(size_t)k * H_DIM + h] * wr;
    }
    WcT[idx] = st;
    WcI[idx] = si;
}

__global__ void bterm_kernel(const float* __restrict__ bt, const float* __restrict__ bi,
                             const float* __restrict__ Wr, const float* __restrict__ br,
                             float* __restrict__ bterm)
{
    int e = threadIdx.x;
    if (e < N_EXP) {
        float sA = 0.f, sB = 0.f;
        for (int h = 0; h < H_DIM; h++) {
            float wr = Wr[h * N_EXP + e];
            sA += (bi[h] + 64.f * bt[h]) * wr;
            sB += (bt[h] + 49.f * bi[h]) * wr;
        }
        bterm[e]         = sA / 65.f + br[e];
        bterm[N_EXP + e] = sB / 50.f + br[e];
    }
}

// -------- router: stage1 bandwidth token-sum (float4), stage2 logits -------
__global__ __launch_bounds__(256) void router2_kernel(
    const float* __restrict__ cls, const float* __restrict__ tok, int Sm1,
    const float* __restrict__ WcCls, const float* __restrict__ WcTok,
    const float* __restrict__ bt,
    int2* __restrict__ eidx, float2* __restrict__ ew)
{
    const int i = blockIdx.x, tid = threadIdx.x;
    __shared__ float sumtok[D_IN];
    __shared__ float red[8][N_EXP];
    __shared__ float logits[N_EXP];

    if (tid < 192) {
        const float4* tp = (const float4*)(tok + (size_t)i * Sm1 * D_IN) + tid;
        float4 s0 = make_float4(0.f, 0.f, 0.f, 0.f), s1 = s0, s2 = s0, s3 = s0;
        int t = 0;
        for (; t + 4 <= Sm1; t += 4) {
            float4 a = tp[(size_t)(t + 0) * 192];
            float4 b = tp[(size_t)(t + 1) * 192];
            float4 c = tp[(size_t)(t + 2) * 192];
            float4 d = tp[(size_t)(t + 3) * 192];
            s0.x += a.x; s0.y += a.y; s0.z += a.z; s0.w += a.w;
            s1.x += b.x; s1.y += b.y; s1.z += b.z; s1.w += b.w;
            s2.x += c.x; s2.y += c.y; s2.z += c.z; s2.w += c.w;
            s3.x += d.x; s3.y += d.y; s3.z += d.z; s3.w += d.w;
        }
        for (; t < Sm1; t++) {
            float4 a = tp[(size_t)t * 192];
            s0.x += a.x; s0.y += a.y; s0.z += a.z; s0.w += a.w;
        }
        float4 s = make_float4(s0.x + s1.x + s2.x + s3.x, s0.y + s1.y + s2.y + s3.y,
                               s0.z + s1.z + s2.z + s3.z, s0.w + s1.w + s2.w + s3.w);
        *(float4*)&sumtok[tid * 4] = s;
    }
    __syncthreads();

    const int warp = tid >> 5, lane = tid & 31;
    {
        float part[N_EXP];
#pragma unroll
        for (int e = 0; e < N_EXP; e++) part[e] = 0.f;
        for (int c = tid; c < D_IN; c += 256) {
            float cl = cls[(size_t)i * D_IN + c];
            float s = sumtok[c];
#pragma unroll
            for (int e = 0; e < N_EXP; e++)
                part[e] += cl * WcCls[c * N_EXP + e] + s * WcTok[c * N_EXP + e];
        }
#pragma unroll
        for (int o = 16; o; o >>= 1)
#pragma unroll
            for (int e = 0; e < N_EXP; e++)
                part[e] += __shfl_down_sync(0xffffffffu, part[e], o);
        if (lane == 0)
#pragma unroll
            for (int e = 0; e < N_EXP; e++) red[warp][e] = part[e];
    }
    __syncthreads();
    if (tid < N_EXP) {
        float l = 0.f;
        for (int wq = 0; wq < 8; wq++) l += red[wq][tid];
        logits[tid] = l / (float)(Sm1 + 1) + bt[tid];
    }
    __syncthreads();
    if (tid == 0) {
        int b0 = 0;
        for (int e = 1; e < N_EXP; e++)
            if (logits[e] > logits[b0]) b0 = e;
        int b1 = (b0 == 0) ? 1 : 0;
        for (int e = 0; e < N_EXP; e++)
            if (e != b0 && logits[e] > logits[b1]) b1 = e;
        float e1v = expf(logits[b1] - logits[b0]);
        float inv = 1.0f / (1.0f + e1v);
        eidx[i] = make_int2(b0, b1);
        ew[i] = make_float2(inv, e1v * inv);
    }
}

// ---------------------- cross attention (vectorized) -----------------------
__global__ __launch_bounds__(256) void cross_kernel(
    const float* __restrict__ moe_out, int S, float* __restrict__ ctx)
{
    const int i = blockIdx.x;
    __shared__ float4 cls4[H_DIM / 4];
    __shared__ float prob[64];
    const int tid = threadIdx.x;
    const float* base = moe_out + (size_t)i * S * H_DIM;

    if (tid < H_DIM / 4) cls4[tid] = ((const float4*)base)[tid];
    __syncthreads();

    const int nt = S - 1;
    const int warp = tid >> 5, lane = tid & 31;
    for (int s = warp; s < nt; s += 8) {
        const float4* tr = (const float4*)(base + (size_t)(s + 1) * H_DIM);
        float p = 0.f;
#pragma unroll
        for (int q = 0; q < 4; q++) {
            float4 a = cls4[lane + 32 * q];
            float4 b = tr[lane + 32 * q];
            p += a.x * b.x + a.y * b.y + a.z * b.z + a.w * b.w;
        }
#pragma unroll
        for (int o = 16; o; o >>= 1) p += __shfl_down_sync(0xffffffffu, p, o);
        if (lane == 0) prob[s] = p;
    }
    __syncthreads();

    if (tid == 0) {
        float mx = -1e30f;
        for (int s = 0; s < nt; s++) mx = fmaxf(mx, prob[s]);
        float sum = 0.f;
        for (int s = 0; s < nt; s++) { float e = expf(prob[s] - mx); prob[s] = e; sum += e; }
        float inv = 1.0f / sum;
        for (int s = 0; s < nt; s++) prob[s] *= inv;
    }
    __syncthreads();

    float2 acc = make_float2(0.f, 0.f);
    const float2* b2 = (const float2*)(base + H_DIM) + tid;
#pragma unroll 4
    for (int s = 0; s < nt; s++) {
        float2 v = b2[(size_t)s * (H_DIM / 2)];
        float pw = prob[s];
        acc.x += pw * v.x; acc.y += pw * v.y;
    }
    ((float2*)(ctx + (size_t)i * H_DIM))[tid] = acc;
}

// --------------------------- gate + residual + LN ---------------------------
__global__ __launch_bounds__(256) void gate_ln_kernel(
    const float* __restrict__ ori, const float* __restrict__ ctx,
    const float* __restrict__ Wg, const float* __restrict__ bg,
    const float* __restrict__ ls, const float* __restrict__ lb,
    float* __restrict__ out, int gate_from_ctx)
{
    const int i = blockIdx.x;
    __shared__ float v[H_DIM];
    __shared__ float red[256];
    const int tid = threadIdx.x;
    const float* orow = ori + (size_t)i * H_DIM;
    const float* crow = ctx + (size_t)i * H_DIM;

    float p = 0.f;
    for (int c = tid; c < H_DIM; c += 256) {
        float gs = gate_from_ctx ? crow[c] : orow[c];
        p += gs * Wg[c];
    }
    red[tid] = p; __syncthreads();
    for (int o = 128; o; o >>= 1) { if (tid < o) red[tid] += red[tid + o]; __syncthreads(); }
    float gate = tanhf(red[0] + bg[0]);
    __syncthreads();

    float sum = 0.f;
    for (int c = tid; c < H_DIM; c += 256) {
        float val = orow[c] * gate + crow[c];
        v[c] = val; sum += val;
    }
    red[tid] = sum; __syncthreads();
    for (int o = 128; o; o >>= 1) { if (tid < o) red[tid] += red[tid + o]; __syncthreads(); }
    float mean = red[0] / (float)H_DIM;
    __syncthreads();

    float var = 0.f;
    for (int c = tid; c < H_DIM; c += 256) { float d = v[c] - mean; var += d * d; }
    red[tid] = var; __syncthreads();
    for (int o = 128; o; o >>= 1) { if (tid < o) red[tid] += red[tid + o]; __syncthreads(); }
    float rstd = rsqrtf(red[0] / (float)H_DIM + 1e-5f);

    for (int c = tid; c < H_DIM; c += 256)
        out[(size_t)i * H_DIM + c] = (v[c] - mean) * rstd * ls[c] + lb[c];
}

// -------------------------------- final score -------------------------------
__global__ __launch_bounds__(256) void score_kernel(
    const float* __restrict__ mti, const float* __restrict__ eti,
    const float* __restrict__ mit, const float* __restrict__ eit,
    float* __restrict__ out)
{
    __shared__ float As[8][64];
    __shared__ float Bs[8][64];
    const int n0 = blockIdx.x * 64;
    const int b0 = blockIdx.y * 64;
    const int tid = threadIdx.x;
    const int tx = tid & 15, ty = tid >> 4;
    const int lrow = tid >> 2, lcol = (tid & 3) * 2;

    float acc[4][4];
#pragma unroll
    for (int q = 0; q < 4; q++)
#pragma unroll
        for (int r = 0; r < 4; r++) acc[q][r] = 0.f;

#pragma unroll
    for (int pass = 0; pass < 2; pass++) {
        const float* A = pass ? mit : mti;
        const float* B = pass ? eit : eti;
        for (int k0 = 0; k0 < H_DIM; k0 += 8) {
            float2 av = *(const float2*)(A + (size_t)(b0 + lrow) * H_DIM + k0 + lcol);
            As[lcol][lrow] = av.x; As[lcol + 1][lrow] = av.y;
            float2 bv = *(const float2*)(B + (size_t)(n0 + lrow) * H_DIM + k0 + lcol);
            Bs[lcol][lrow] = bv.x; Bs[lcol + 1][lrow] = bv.y;
            __syncthreads();
#pragma unroll
            for (int k = 0; k < 8; k++) {
                float a[4], b[4];
#pragma unroll
                for (int q = 0; q < 4; q++) a[q] = As[k][ty * 4 + q];
#pragma unroll
                for (int q = 0; q < 4; q++) b[q] = Bs[k][tx * 4 + q];
#pragma unroll
                for (int q = 0; q < 4; q++)
#pragma unroll
                    for (int r = 0; r < 4; r++) acc[q][r] += a[q] * b[r];
            }
            __syncthreads();
        }
    }
#pragma unroll
    for (int q = 0; q < 4; q++)
#pragma unroll
        for (int r = 0; r < 4; r++)
            out[(size_t)(b0 + ty * 4 + q) * N_ENT + (n0 + tx * 4 + r)] = 0.5f * acc[q][r];
}

// ---------------------------------- launch ----------------------------------
extern "C" void kernel_launch(void* const* d_in, const int* in_sizes, int n_in,
                              void* d_out, int out_size)
{
    const float* etc_in = (const float*)d_in[0];
    const float* ett_in = (const float*)d_in[1];
    const float* mtc_in = (const float*)d_in[2];
    const float* mtt_in = (const float*)d_in[3];
    const float* eic_in = (const float*)d_in[4];
    const float* eit_in = (const float*)d_in[5];
    const float* mic_in = (const float*)d_in[6];
    const float* mit_in = (const float*)d_in[7];
    const float* W_text = (const float*)d_in[8];
    const float* b_text = (const float*)d_in[9];
    const float* W_img  = (const float*)d_in[10];
    const float* b_img  = (const float*)d_in[11];
    const float* W_gate = (const float*)d_in[12];
    const float* b_gate = (const float*)d_in[13];
    const float* ln_s   = (const float*)d_in[14];
    const float* ln_b   = (const float*)d_in[15];
    const float* W_rout = (const float*)d_in[16];
    const float* b_rout = (const float*)d_in[17];
    const float* W_exp  = (const float*)d_in[18];
    const float* b_exp  = (const float*)d_in[19];
    float* out = (float*)d_out;

    float *p_etc, *p_eic, *p_mtc, *p_mic, *p_ett, *p_eit, *p_mtt, *p_mit;
    float *p_etim, *p_mtim, *p_eitm, *p_mitm;
    float *p_ctx0, *p_ctx1, *p_ctx2, *p_ctx3;
    float *p_feti, *p_fmti, *p_feit, *p_fmit;
    float *p_wct, *p_wci, *p_bt;
    int2* p_eidx; float2* p_ew;
    cudaGetSymbolAddress((void**)&p_etc, g_etc);
    cudaGetSymbolAddress((void**)&p_eic, g_eic);
    cudaGetSymbolAddress((void**)&p_mtc, g_mtc);
    cudaGetSymbolAddress((void**)&p_mic, g_mic);
    cudaGetSymbolAddress((void**)&p_ett, g_ett);
    cudaGetSymbolAddress((void**)&p_eit, g_eit);
    cudaGetSymbolAddress((void**)&p_mtt, g_mtt);
    cudaGetSymbolAddress((void**)&p_mit, g_mit);
    cudaGetSymbolAddress((void**)&p_etim, g_eti_m);
    cudaGetSymbolAddress((void**)&p_mtim, g_mti_m);
    cudaGetSymbolAddress((void**)&p_eitm, g_eit_m);
    cudaGetSymbolAddress((void**)&p_mitm, g_mit_m);
    cudaGetSymbolAddress((void**)&p_ctx0, g_ctx0);
    cudaGetSymbolAddress((void**)&p_ctx1, g_ctx1);
    cudaGetSymbolAddress((void**)&p_ctx2, g_ctx2);
    cudaGetSymbolAddress((void**)&p_ctx3, g_ctx3);
    cudaGetSymbolAddress((void**)&p_feti, g_fe_ti);
    cudaGetSymbolAddress((void**)&p_fmti, g_fm_ti);
    cudaGetSymbolAddress((void**)&p_feit, g_fe_it);
    cudaGetSymbolAddress((void**)&p_fmit, g_fm_it);
    cudaGetSymbolAddress((void**)&p_wct, g_wc_text);
    cudaGetSymbolAddress((void**)&p_wci, g_wc_img);
    cudaGetSymbolAddress((void**)&p_bt, g_bterm);
    cudaGetSymbolAddress((void**)&p_eidx, g_eidx);
    cudaGetSymbolAddress((void**)&p_ew,   g_ew);

    dim3 blk(256);
    dim3 blkg(128);

    // 1-2: router weight folding
    combine_w_kernel<<<(D_IN * N_EXP + 255) / 256, blk>>>(W_text, W_img, W_rout, p_wct, p_wci);
    bterm_kernel<<<1, 32>>>(b_text, b_img, W_rout, b_rout, p_bt);

    // 3: first big router
    router2_kernel<<<N_ENT, blk>>>(eic_in, ett_in, T_TOK, p_wci, p_wct, p_bt,
                                   p_eidx + 0 * N_ENT, p_ew + 0 * N_ENT);

    // 4: big ett projection — positioned for ncu capture
    proj_tc<<<dim3(N_ENT * T_TOK / 128, 4), blkg>>>(ett_in, W_text, b_text, p_ett, N_ENT * T_TOK);

    // remaining routers
    router2_kernel<<<BATCH, blk>>>(mic_in, mtt_in, T_TOK, p_wci, p_wct, p_bt,
                                   p_eidx + 1 * N_ENT, p_ew + 1 * N_ENT);
    router2_kernel<<<N_ENT, blk>>>(etc_in, eit_in, P_TOK, p_wct, p_wci, p_bt + N_EXP,
                                   p_eidx + 2 * N_ENT, p_ew + 2 * N_ENT);
    router2_kernel<<<BATCH, blk>>>(mtc_in, mit_in, P_TOK, p_wct, p_wci, p_bt + N_EXP,
                                   p_eidx + 3 * N_ENT, p_ew + 3 * N_ENT);

    // remaining projections
    proj_tc<<<dim3(N_ENT / 128, 4), blkg>>>(etc_in, W_text, b_text, p_etc, N_ENT);
    proj_tc<<<dim3(BATCH / 128, 4), blkg>>>(mtc_in, W_text, b_text, p_mtc, BATCH);
    proj_tc<<<dim3(BATCH * T_TOK / 128, 4), blkg>>>(mtt_in, W_text, b_text, p_mtt, BATCH * T_TOK);
    proj_tc<<<dim3(N_ENT / 128, 4), blkg>>>(eic_in, W_img, b_img, p_eic, N_ENT);
    proj_tc<<<dim3(N_ENT * P_TOK / 128, 4), blkg>>>(eit_in, W_img, b_img, p_eit, N_ENT * P_TOK);
    proj_tc<<<dim3(BATCH / 128, 4), blkg>>>(mic_in, W_img, b_img, p_mic, BATCH);
    proj_tc<<<dim3(BATCH * P_TOK / 128, 4), blkg>>>(mit_in, W_img, b_img, p_mit, BATCH * P_TOK);

    // MoE GEMMs (combined expert pair, 3xTF32)
    moe2_tc<<<dim3(2, 1, N_ENT), blkg>>>(p_etc, p_eit, W_exp, b_exp,
                                         p_eidx + 0 * N_ENT, p_ew + 0 * N_ENT, p_etim);
    moe2_tc<<<dim3(2, 1, BATCH), blkg>>>(p_mtc, p_mit, W_exp, b_exp,
                                         p_eidx + 1 * N_ENT, p_ew + 1 * N_ENT, p_mtim);
    moe3_tc<<<dim3(4, 1, N_ENT), blkg>>>(p_eic, p_ett, W_exp, b_exp,
                                         p_eidx + 2 * N_ENT, p_ew + 2 * N_ENT, p_eitm);
    moe3_tc<<<dim3(4, 1, BATCH), blkg>>>(p_mic, p_mtt, W_exp, b_exp,
                                         p_eidx + 3 * N_ENT, p_ew + 3 * N_ENT, p_mitm);

    // cross attention
    cross_kernel<<<N_ENT, blk>>>(p_etim, 50, p_ctx0);
    cross_kernel<<<BATCH, blk>>>(p_mtim, 50, p_ctx1);
    cross_kernel<<<N_ENT, blk>>>(p_eitm, 65, p_ctx2);
    cross_kernel<<<BATCH, blk>>>(p_mitm, 65, p_ctx3);

    // gate + residual + LN
    gate_ln_kernel<<<N_ENT, blk>>>(p_etc, p_ctx0, W_gate, b_gate, ln_s, ln_b, p_feti, 1);
    gate_ln_kernel<<<BATCH, blk>>>(p_mtc, p_ctx1, W_gate, b_gate, ln_s, ln_b, p_fmti, 0);
    gate_ln_kernel<<<N_ENT, blk>>>(p_eic, p_ctx2, W_gate, b_gate, ln_s, ln_b, p_feit, 1);
    gate_ln_kernel<<<BATCH, blk>>>(p_mic, p_ctx3, W_gate, b_gate, ln_s, ln_b, p_fmit, 0);

    // final score
    score_kernel<<<dim3(N_ENT / 64, BATCH / 64), blk>>>(p_fmti, p_feti, p_fmit, p_feit, out);
}

// round 10
// speedup vs baseline: 1.3001x; 1.3001x over previous
#include <cuda_runtime.h>
#include <cuda_bf16.h>
#include <math.h>
#include <stdint.h>

#define N_ENT 1024
#define BATCH 128
#define T_TOK 64
#define P_TOK 49
#define D_IN 768
#define H_DIM 512
#define N_EXP 8

// ----------------------------- static scratch ------------------------------
__device__ float g_etc[N_ENT * H_DIM];
__device__ float g_eic[N_ENT * H_DIM];
__device__ float g_mtc[BATCH * H_DIM];
__device__ float g_mic[BATCH * H_DIM];
__device__ float g_ett[N_ENT * T_TOK * H_DIM];
__device__ float g_eit[N_ENT * P_TOK * H_DIM];
__device__ float g_mtt[BATCH * T_TOK * H_DIM];
__device__ float g_mit[BATCH * P_TOK * H_DIM];

__device__ float g_eti_m[N_ENT * 50 * H_DIM];
__device__ float g_mti_m[BATCH * 50 * H_DIM];
__device__ float g_eit_m[N_ENT * 65 * H_DIM];
__device__ float g_mit_m[BATCH * 65 * H_DIM];

__device__ int2   g_eidx[4][N_ENT];
__device__ float2 g_ew[4][N_ENT];

__device__ float g_ctx0[N_ENT * H_DIM];
__device__ float g_ctx1[BATCH * H_DIM];
__device__ float g_ctx2[N_ENT * H_DIM];
__device__ float g_ctx3[BATCH * H_DIM];

__device__ float g_fe_ti[N_ENT * H_DIM];
__device__ float g_fm_ti[BATCH * H_DIM];
__device__ float g_fe_it[N_ENT * H_DIM];
__device__ float g_fm_it[BATCH * H_DIM];

__device__ float g_wc_text[D_IN * N_EXP];
__device__ float g_wc_img[D_IN * N_EXP];
__device__ float g_bterm[2 * N_EXP];

// --------------------------- bf16 split helpers -----------------------------
// x = h + l, h/l bf16; pack 2 elements per uint32 (low 16 bits = first elem).
__device__ __forceinline__ void split_bf16x2(float a, float b, uint32_t& h, uint32_t& l)
{
    __nv_bfloat162 hp = __floats2bfloat162_rn(a, b);
    float ra = a - __bfloat162float(hp.x);
    float rb = b - __bfloat162float(hp.y);
    __nv_bfloat162 lp = __floats2bfloat162_rn(ra, rb);
    h = *(uint32_t*)&hp;
    l = *(uint32_t*)&lp;
}

// two K-adjacent rows (r0 = k even, r1 = k odd) x 4 columns -> 4 packed pairs
__device__ __forceinline__ void splitB4(float4 r0, float4 r1, uint4& h, uint4& l)
{
    split_bf16x2(r0.x, r1.x, h.x, l.x);
    split_bf16x2(r0.y, r1.y, h.y, l.y);
    split_bf16x2(r0.z, r1.z, h.z, l.z);
    split_bf16x2(r0.w, r1.w, h.w, l.w);
}

__device__ __forceinline__ void mma16(float* c, const uint32_t* a, const uint32_t* b)
{
    asm volatile(
        "mma.sync.aligned.m16n8k16.row.col.f32.bf16.bf16.f32 "
        "{%0,%1,%2,%3}, {%4,%5,%6,%7}, {%8,%9}, {%0,%1,%2,%3};"
        : "+f"(c[0]), "+f"(c[1]), "+f"(c[2]), "+f"(c[3])
        : "r"(a[0]), "r"(a[1]), "r"(a[2]), "r"(a[3]), "r"(b[0]), "r"(b[1]));
}

#define ASTRP 12    // pairs per row (8) + pad: gid*12+tig all distinct mod 32
#define BSTRP 136   // 136 mod 32 == 8 -> 8*tig+gid distinct
#define BSTRP2 264  // 264 mod 32 == 8

// ----------------- proj (bf16x3): C[M,512]=A[M,768]@W+bias -----------------
// 128 threads, block 128x128, 4 warps of 64x64, 2 CTAs/SM. BK=16 (1 k-step).
__global__ __launch_bounds__(128, 2) void proj_tc(
    const float* __restrict__ A, const float* __restrict__ W,
    const float* __restrict__ bias, float* __restrict__ C, int M)
{
    __shared__ uint32_t AsH[128 * ASTRP], AsL[128 * ASTRP];
    __shared__ uint32_t BsH[8 * BSTRP], BsL[8 * BSTRP];

    const int tid = threadIdx.x;
    const int row0 = blockIdx.x * 128;
    const int col0 = blockIdx.y * 128;
    const int warp = tid >> 5, lane = tid & 31;
    const int wm = warp >> 1, wn = warp & 1;
    const int gid = lane >> 2, tig = lane & 3;
    const int bk = tid >> 4;            // B pair-row 0..7
    const int nc = (tid & 15) * 8;      // B col group

    float acc[4][8][4];
#pragma unroll
    for (int a = 0; a < 4; a++)
#pragma unroll
        for (int b = 0; b < 8; b++)
#pragma unroll
            for (int c = 0; c < 4; c++) acc[a][b][c] = 0.f;

    const float* Arow = A + (size_t)(row0 + tid) * D_IN;

    for (int kb = 0; kb < D_IN / 16; kb++) {
        const int k0 = kb * 16;
        // ---- A: 16 k-values -> 8 packed pairs ----
#pragma unroll
        for (int q = 0; q < 4; q++) {
            float4 v = *(const float4*)(Arow + k0 + q * 4);
            uint32_t h0, l0, h1, l1;
            split_bf16x2(v.x, v.y, h0, l0);
            split_bf16x2(v.z, v.w, h1, l1);
            *(uint2*)&AsH[tid * ASTRP + q * 2] = make_uint2(h0, h1);
            *(uint2*)&AsL[tid * ASTRP + q * 2] = make_uint2(l0, l1);
        }
        // ---- B: pair rows (k0+2bk, k0+2bk+1), 8 cols ----
        {
            const float* Wr = W + (size_t)(k0 + 2 * bk) * H_DIM + col0 + nc;
            float4 r0a = *(const float4*)(Wr);
            float4 r0b = *(const float4*)(Wr + 4);
            float4 r1a = *(const float4*)(Wr + H_DIM);
            float4 r1b = *(const float4*)(Wr + H_DIM + 4);
            uint4 h, l;
            splitB4(r0a, r1a, h, l);
            *(uint4*)&BsH[bk * BSTRP + nc] = h;
            *(uint4*)&BsL[bk * BSTRP + nc] = l;
            splitB4(r0b, r1b, h, l);
            *(uint4*)&BsH[bk * BSTRP + nc + 4] = h;
            *(uint4*)&BsL[bk * BSTRP + nc + 4] = l;
        }
        __syncthreads();

        uint32_t ah[4][4], al[4][4], bh[8][2], bl[8][2];
#pragma unroll
        for (int mt = 0; mt < 4; mt++) {
            int r = (wm * 64 + mt * 16 + gid) * ASTRP;
            ah[mt][0] = AsH[r + tig];              ah[mt][1] = AsH[r + 8 * ASTRP + tig];
            ah[mt][2] = AsH[r + tig + 4];          ah[mt][3] = AsH[r + 8 * ASTRP + tig + 4];
            al[mt][0] = AsL[r + tig];              al[mt][1] = AsL[r + 8 * ASTRP + tig];
            al[mt][2] = AsL[r + tig + 4];          al[mt][3] = AsL[r + 8 * ASTRP + tig + 4];
        }
#pragma unroll
        for (int nt = 0; nt < 8; nt++) {
            int c = wn * 64 + nt * 8 + gid;
            bh[nt][0] = BsH[tig * BSTRP + c]; bh[nt][1] = BsH[(tig + 4) * BSTRP + c];
            bl[nt][0] = BsL[tig * BSTRP + c]; bl[nt][1] = BsL[(tig + 4) * BSTRP + c];
        }
#pragma unroll
        for (int mt = 0; mt < 4; mt++)
#pragma unroll
            for (int nt = 0; nt < 8; nt++) mma16(acc[mt][nt], ah[mt], bh[nt]);
#pragma unroll
        for (int mt = 0; mt < 4; mt++)
#pragma unroll
            for (int nt = 0; nt < 8; nt++) mma16(acc[mt][nt], ah[mt], bl[nt]);
#pragma unroll
        for (int mt = 0; mt < 4; mt++)
#pragma unroll
            for (int nt = 0; nt < 8; nt++) mma16(acc[mt][nt], al[mt], bh[nt]);
        __syncthreads();
    }

#pragma unroll
    for (int mt = 0; mt < 4; mt++) {
        int m = row0 + wm * 64 + mt * 16 + gid;
#pragma unroll
        for (int nt = 0; nt < 8; nt++) {
            int n = col0 + wn * 64 + nt * 8 + tig * 2;
            float2 bv = *(const float2*)(bias + n);
            *(float2*)(C + (size_t)m * H_DIM + n) =
                make_float2(acc[mt][nt][0] + bv.x, acc[mt][nt][1] + bv.y);
            *(float2*)(C + (size_t)(m + 8) * H_DIM + n) =
                make_float2(acc[mt][nt][2] + bv.x, acc[mt][nt][3] + bv.y);
        }
    }
}

// -------- MoE S=50 (bf16x3): block 64x256, 4 warps of 64x64 ----------------
__global__ __launch_bounds__(128, 2) void moe2_tc(
    const float* __restrict__ cls, const float* __restrict__ tok,
    const float* __restrict__ We, const float* __restrict__ be,
    const int2* __restrict__ eidx, const float2* __restrict__ ew,
    float* __restrict__ out)
{
    const int S = 50;
    __shared__ uint32_t AsH[64 * ASTRP], AsL[64 * ASTRP];
    __shared__ uint32_t BsH[8 * BSTRP2], BsL[8 * BSTRP2];

    const int i = blockIdx.z;
    const int col0 = blockIdx.x * 256;
    const int2 e = eidx[i];
    const float2 w = ew[i];
    const float* W0 = We + (size_t)e.x * H_DIM * H_DIM;
    const float* W1 = We + (size_t)e.y * H_DIM * H_DIM;

    const int tid = threadIdx.x;
    const int warp = tid >> 5, lane = tid & 31;
    const int wn = warp;
    const int gid = lane >> 2, tig = lane & 3;
    const int bk = tid >> 4;              // B pair-row 0..7
    const int nc = (tid & 15) * 16;       // 16 cols per thread (256 total)
    const int arow = tid & 63, ahalf = tid >> 6;

    const float* rp = nullptr;
    if (arow < S)
        rp = (arow == 0) ? (cls + (size_t)i * H_DIM)
                         : (tok + ((size_t)i * (S - 1) + (arow - 1)) * H_DIM);

    float acc[4][8][4];
#pragma unroll
    for (int a = 0; a < 4; a++)
#pragma unroll
        for (int b = 0; b < 8; b++)
#pragma unroll
            for (int c = 0; c < 4; c++) acc[a][b][c] = 0.f;

    for (int kb = 0; kb < H_DIM / 16; kb++) {
        const int k0 = kb * 16;
        // A: 2 threads per row, 8 k-values each -> 4 pairs
#pragma unroll
        for (int q = 0; q < 2; q++) {
            float4 v = make_float4(0.f, 0.f, 0.f, 0.f);
            if (rp) v = *(const float4*)(rp + k0 + ahalf * 8 + q * 4);
            uint32_t h0, l0, h1, l1;
            split_bf16x2(v.x, v.y, h0, l0);
            split_bf16x2(v.z, v.w, h1, l1);
            *(uint2*)&AsH[arow * ASTRP + ahalf * 4 + q * 2] = make_uint2(h0, h1);
            *(uint2*)&AsL[arow * ASTRP + ahalf * 4 + q * 2] = make_uint2(l0, l1);
        }
        // B: combine experts then split; pair rows (k0+2bk, +1), 16 cols
        {
            size_t o0 = (size_t)(k0 + 2 * bk) * H_DIM + col0 + nc;
#pragma unroll
            for (int q = 0; q < 4; q++) {
                float4 a0 = *(const float4*)(W0 + o0 + q * 4);
                float4 b0 = *(const float4*)(W1 + o0 + q * 4);
                float4 a1 = *(const float4*)(W0 + o0 + H_DIM + q * 4);
                float4 b1 = *(const float4*)(W1 + o0 + H_DIM + q * 4);
                float4 r0 = make_float4(w.x * a0.x + w.y * b0.x, w.x * a0.y + w.y * b0.y,
                                        w.x * a0.z + w.y * b0.z, w.x * a0.w + w.y * b0.w);
                float4 r1 = make_float4(w.x * a1.x + w.y * b1.x, w.x * a1.y + w.y * b1.y,
                                        w.x * a1.z + w.y * b1.z, w.x * a1.w + w.y * b1.w);
                uint4 h, l;
                splitB4(r0, r1, h, l);
                *(uint4*)&BsH[bk * BSTRP2 + nc + q * 4] = h;
                *(uint4*)&BsL[bk * BSTRP2 + nc + q * 4] = l;
            }
        }
        __syncthreads();

        uint32_t ah[4][4], al[4][4], bh[8][2], bl[8][2];
#pragma unroll
        for (int mt = 0; mt < 4; mt++) {
            int r = (mt * 16 + gid) * ASTRP;
            ah[mt][0] = AsH[r + tig];     ah[mt][1] = AsH[r + 8 * ASTRP + tig];
            ah[mt][2] = AsH[r + tig + 4]; ah[mt][3] = AsH[r + 8 * ASTRP + tig + 4];
            al[mt][0] = AsL[r + tig];     al[mt][1] = AsL[r + 8 * ASTRP + tig];
            al[mt][2] = AsL[r + tig + 4]; al[mt][3] = AsL[r + 8 * ASTRP + tig + 4];
        }
#pragma unroll
        for (int nt = 0; nt < 8; nt++) {
            int c = wn * 64 + nt * 8 + gid;
            bh[nt][0] = BsH[tig * BSTRP2 + c]; bh[nt][1] = BsH[(tig + 4) * BSTRP2 + c];
            bl[nt][0] = BsL[tig * BSTRP2 + c]; bl[nt][1] = BsL[(tig + 4) * BSTRP2 + c];
        }
#pragma unroll
        for (int mt = 0; mt < 4; mt++)
#pragma unroll
            for (int nt = 0; nt < 8; nt++) mma16(acc[mt][nt], ah[mt], bh[nt]);
#pragma unroll
        for (int mt = 0; mt < 4; mt++)
#pragma unroll
            for (int nt = 0; nt < 8; nt++) mma16(acc[mt][nt], ah[mt], bl[nt]);
#pragma unroll
        for (int mt = 0; mt < 4; mt++)
#pragma unroll
            for (int nt = 0; nt < 8; nt++) mma16(acc[mt][nt], al[mt], bh[nt]);
        __syncthreads();
    }

#pragma unroll
    for (int mt = 0; mt < 4; mt++) {
        int t = mt * 16 + gid;
#pragma unroll
        for (int nt = 0; nt < 8; nt++) {
            int n = col0 + wn * 64 + nt * 8 + tig * 2;
            float b0 = w.x * be[e.x * H_DIM + n]     + w.y * be[e.y * H_DIM + n];
            float b1 = w.x * be[e.x * H_DIM + n + 1] + w.y * be[e.y * H_DIM + n + 1];
            if (t < S)
                *(float2*)(out + ((size_t)i * S + t) * H_DIM + n) =
                    make_float2(acc[mt][nt][0] + b0, acc[mt][nt][1] + b1);
            if (t + 8 < S)
                *(float2*)(out + ((size_t)i * S + t + 8) * H_DIM + n) =
                    make_float2(acc[mt][nt][2] + b0, acc[mt][nt][3] + b1);
        }
    }
}

// -------- MoE S=65 (bf16x3): block 96x128, 4 warps of 48x64 ----------------
__global__ __launch_bounds__(128, 2) void moe3_tc(
    const float* __restrict__ cls, const float* __restrict__ tok,
    const float* __restrict__ We, const float* __restrict__ be,
    const int2* __restrict__ eidx, const float2* __restrict__ ew,
    float* __restrict__ out)
{
    const int S = 65;
    __shared__ uint32_t AsH[96 * ASTRP], AsL[96 * ASTRP];
    __shared__ uint32_t BsH[8 * BSTRP], BsL[8 * BSTRP];

    const int i = blockIdx.z;
    const int col0 = blockIdx.x * 128;
    const int2 e = eidx[i];
    const float2 w = ew[i];
    const float* W0 = We + (size_t)e.x * H_DIM * H_DIM;
    const float* W1 = We + (size_t)e.y * H_DIM * H_DIM;

    const int tid = threadIdx.x;
    const int warp = tid >> 5, lane = tid & 31;
    const int wm = warp >> 1, wn = warp & 1;
    const int gid = lane >> 2, tig = lane & 3;
    const int bk = tid >> 4;
    const int nc = (tid & 15) * 8;

    const float* rp = nullptr;
    if (tid < S)
        rp = (tid == 0) ? (cls + (size_t)i * H_DIM)
                        : (tok + ((size_t)i * (S - 1) + (tid - 1)) * H_DIM);

    float acc[3][8][4];
#pragma unroll
    for (int a = 0; a < 3; a++)
#pragma unroll
        for (int b = 0; b < 8; b++)
#pragma unroll
            for (int c = 0; c < 4; c++) acc[a][b][c] = 0.f;

    for (int kb = 0; kb < H_DIM / 16; kb++) {
        const int k0 = kb * 16;
        if (tid < 96) {
#pragma unroll
            for (int q = 0; q < 4; q++) {
                float4 v = make_float4(0.f, 0.f, 0.f, 0.f);
                if (rp) v = *(const float4*)(rp + k0 + q * 4);
                uint32_t h0, l0, h1, l1;
                split_bf16x2(v.x, v.y, h0, l0);
                split_bf16x2(v.z, v.w, h1, l1);
                *(uint2*)&AsH[tid * ASTRP + q * 2] = make_uint2(h0, h1);
                *(uint2*)&AsL[tid * ASTRP + q * 2] = make_uint2(l0, l1);
            }
        }
        {
            size_t o0 = (size_t)(k0 + 2 * bk) * H_DIM + col0 + nc;
#pragma unroll
            for (int q = 0; q < 2; q++) {
                float4 a0 = *(const float4*)(W0 + o0 + q * 4);
                float4 b0 = *(const float4*)(W1 + o0 + q * 4);
                float4 a1 = *(const float4*)(W0 + o0 + H_DIM + q * 4);
                float4 b1 = *(const float4*)(W1 + o0 + H_DIM + q * 4);
                float4 r0 = make_float4(w.x * a0.x + w.y * b0.x, w.x * a0.y + w.y * b0.y,
                                        w.x * a0.z + w.y * b0.z, w.x * a0.w + w.y * b0.w);
                float4 r1 = make_float4(w.x * a1.x + w.y * b1.x, w.x * a1.y + w.y * b1.y,
                                        w.x * a1.z + w.y * b1.z, w.x * a1.w + w.y * b1.w);
                uint4 h, l;
                splitB4(r0, r1, h, l);
                *(uint4*)&BsH[bk * BSTRP + nc + q * 4] = h;
                *(uint4*)&BsL[bk * BSTRP + nc + q * 4] = l;
            }
        }
        __syncthreads();

        uint32_t ah[3][4], al[3][4], bh[8][2], bl[8][2];
#pragma unroll
        for (int mt = 0; mt < 3; mt++) {
            int r = (wm * 48 + mt * 16 + gid) * ASTRP;
            ah[mt][0] = AsH[r + tig];     ah[mt][1] = AsH[r + 8 * ASTRP + tig];
            ah[mt][2] = AsH[r + tig + 4]; ah[mt][3] = AsH[r + 8 * ASTRP + tig + 4];
            al[mt][0] = AsL[r + tig];     al[mt][1] = AsL[r + 8 * ASTRP + tig];
            al[mt][2] = AsL[r + tig + 4]; al[mt][3] = AsL[r + 8 * ASTRP + tig + 4];
        }
#pragma unroll
        for (int nt = 0; nt < 8; nt++) {
            int c = wn * 64 + nt * 8 + gid;
            bh[nt][0] = BsH[tig * BSTRP + c]; bh[nt][1] = BsH[(tig + 4) * BSTRP + c];
            bl[nt][0] = BsL[tig * BSTRP + c]; bl[nt][1] = BsL[(tig + 4) * BSTRP + c];
        }
#pragma unroll
        for (int mt = 0; mt < 3; mt++)
#pragma unroll
            for (int nt = 0; nt < 8; nt++) mma16(acc[mt][nt], ah[mt], bh[nt]);
#pragma unroll
        for (int mt = 0; mt < 3; mt++)
#pragma unroll
            for (int nt = 0; nt < 8; nt++) mma16(acc[mt][nt], ah[mt], bl[nt]);
#pragma unroll
        for (int mt = 0; mt < 3; mt++)
#pragma unroll
            for (int nt = 0; nt < 8; nt++) mma16(acc[mt][nt], al[mt], bh[nt]);
        __syncthreads();
    }

#pragma unroll
    for (int mt = 0; mt < 3; mt++) {
        int t = wm * 48 + mt * 16 + gid;
#pragma unroll
        for (int nt = 0; nt < 8; nt++) {
            int n = col0 + wn * 64 + nt * 8 + tig * 2;
            float b0 = w.x * be[e.x * H_DIM + n]     + w.y * be[e.y * H_DIM + n];
            float b1 = w.x * be[e.x * H_DIM + n + 1] + w.y * be[e.y * H_DIM + n + 1];
            if (t < S)
                *(float2*)(out + ((size_t)i * S + t) * H_DIM + n) =
                    make_float2(acc[mt][nt][0] + b0, acc[mt][nt][1] + b1);
            if (t + 8 < S)
                *(float2*)(out + ((size_t)i * S + t + 8) * H_DIM + n) =
                    make_float2(acc[mt][nt][2] + b0, acc[mt][nt][3] + b1);
        }
    }
}

// --------------------- router weight folding (fp32-exact) ------------------
__global__ void combine_w_kernel(const float* __restrict__ Wt, const float* __restrict__ Wi,
                                 const float* __restrict__ Wr,
                                 float* __restrict__ WcT, float* __restrict__ WcI)
{
    int idx = blockIdx.x * blockDim.x + threadIdx.x;
    if (idx >= D_IN * N_EXP) return;
    int k = idx >> 3, e = idx & 7;
    float st = 0.f, si = 0.f;
    for (int h = 0; h < H_DIM; h++) {
        float wr = Wr[h * N_EXP + e];
        st += Wt[(size_t)k * H_DIM + h] * wr;
        si += Wi[(size_t)k * H_DIM + h] * wr;
    }
    WcT[idx] = st;
    WcI[idx] = si;
}

__global__ void bterm_kernel(const float* __restrict__ bt, const float* __restrict__ bi,
                             const float* __restrict__ Wr, const float* __restrict__ br,
                             float* __restrict__ bterm)
{
    int e = threadIdx.x;
    if (e < N_EXP) {
        float sA = 0.f, sB = 0.f;
        for (int h = 0; h < H_DIM; h++) {
            float wr = Wr[h * N_EXP + e];
            sA += (bi[h] + 64.f * bt[h]) * wr;
            sB += (bt[h] + 49.f * bi[h]) * wr;
        }
        bterm[e]         = sA / 65.f + br[e];
        bterm[N_EXP + e] = sB / 50.f + br[e];
    }
}

// -------- router: stage1 bandwidth token-sum (float4), stage2 logits -------
__global__ __launch_bounds__(256) void router2_kernel(
    const float* __restrict__ cls, const float* __restrict__ tok, int Sm1,
    const float* __restrict__ WcCls, const float* __restrict__ WcTok,
    const float* __restrict__ bt,
    int2* __restrict__ eidx, float2* __restrict__ ew)
{
    const int i = blockIdx.x, tid = threadIdx.x;
    __shared__ float sumtok[D_IN];
    __shared__ float red[8][N_EXP];
    __shared__ float logits[N_EXP];

    if (tid < 192) {
        const float4* tp = (const float4*)(tok + (size_t)i * Sm1 * D_IN) + tid;
        float4 s0 = make_float4(0.f, 0.f, 0.f, 0.f), s1 = s0, s2 = s0, s3 = s0;
        int t = 0;
        for (; t + 4 <= Sm1; t += 4) {
            float4 a = tp[(size_t)(t + 0) * 192];
            float4 b = tp[(size_t)(t + 1) * 192];
            float4 c = tp[(size_t)(t + 2) * 192];
            float4 d = tp[(size_t)(t + 3) * 192];
            s0.x += a.x; s0.y += a.y; s0.z += a.z; s0.w += a.w;
            s1.x += b.x; s1.y += b.y; s1.z += b.z; s1.w += b.w;
            s2.x += c.x; s2.y += c.y; s2.z += c.z; s2.w += c.w;
            s3.x += d.x; s3.y += d.y; s3.z += d.z; s3.w += d.w;
        }
        for (; t < Sm1; t++) {
            float4 a = tp[(size_t)t * 192];
            s0.x += a.x; s0.y += a.y; s0.z += a.z; s0.w += a.w;
        }
        float4 s = make_float4(s0.x + s1.x + s2.x + s3.x, s0.y + s1.y + s2.y + s3.y,
                               s0.z + s1.z + s2.z + s3.z, s0.w + s1.w + s2.w + s3.w);
        *(float4*)&sumtok[tid * 4] = s;
    }
    __syncthreads();

    const int warp = tid >> 5, lane = tid & 31;
    {
        float part[N_EXP];
#pragma unroll
        for (int e = 0; e < N_EXP; e++) part[e] = 0.f;
        for (int c = tid; c < D_IN; c += 256) {
            float cl = cls[(size_t)i * D_IN + c];
            float s = sumtok[c];
#pragma unroll
            for (int e = 0; e < N_EXP; e++)
                part[e] += cl * WcCls[c * N_EXP + e] + s * WcTok[c * N_EXP + e];
        }
#pragma unroll
        for (int o = 16; o; o >>= 1)
#pragma unroll
            for (int e = 0; e < N_EXP; e++)
                part[e] += __shfl_down_sync(0xffffffffu, part[e], o);
        if (lane == 0)
#pragma unroll
            for (int e = 0; e < N_EXP; e++) red[warp][e] = part[e];
    }
    __syncthreads();
    if (tid < N_EXP) {
        float l = 0.f;
        for (int wq = 0; wq < 8; wq++) l += red[wq][tid];
        logits[tid] = l / (float)(Sm1 + 1) + bt[tid];
    }
    __syncthreads();
    if (tid == 0) {
        int b0 = 0;
        for (int e = 1; e < N_EXP; e++)
            if (logits[e] > logits[b0]) b0 = e;
        int b1 = (b0 == 0) ? 1 : 0;
        for (int e = 0; e < N_EXP; e++)
            if (e != b0 && logits[e] > logits[b1]) b1 = e;
        float e1v = expf(logits[b1] - logits[b0]);
        float inv = 1.0f / (1.0f + e1v);
        eidx[i] = make_int2(b0, b1);
        ew[i] = make_float2(inv, e1v * inv);
    }
}

// ---------------------- cross attention (vectorized) -----------------------
__global__ __launch_bounds__(256) void cross_kernel(
    const float* __restrict__ moe_out, int S, float* __restrict__ ctx)
{
    const int i = blockIdx.x;
    __shared__ float4 cls4[H_DIM / 4];
    __shared__ float prob[64];
    const int tid = threadIdx.x;
    const float* base = moe_out + (size_t)i * S * H_DIM;

    if (tid < H_DIM / 4) cls4[tid] = ((const float4*)base)[tid];
    __syncthreads();

    const int nt = S - 1;
    const int warp = tid >> 5, lane = tid & 31;
    for (int s = warp; s < nt; s += 8) {
        const float4* tr = (const float4*)(base + (size_t)(s + 1) * H_DIM);
        float p = 0.f;
#pragma unroll
        for (int q = 0; q < 4; q++) {
            float4 a = cls4[lane + 32 * q];
            float4 b = tr[lane + 32 * q];
            p += a.x * b.x + a.y * b.y + a.z * b.z + a.w * b.w;
        }
#pragma unroll
        for (int o = 16; o; o >>= 1) p += __shfl_down_sync(0xffffffffu, p, o);
        if (lane == 0) prob[s] = p;
    }
    __syncthreads();

    if (tid == 0) {
        float mx = -1e30f;
        for (int s = 0; s < nt; s++) mx = fmaxf(mx, prob[s]);
        float sum = 0.f;
        for (int s = 0; s < nt; s++) { float e = expf(prob[s] - mx); prob[s] = e; sum += e; }
        float inv = 1.0f / sum;
        for (int s = 0; s < nt; s++) prob[s] *= inv;
    }
    __syncthreads();

    float2 acc = make_float2(0.f, 0.f);
    const float2* b2 = (const float2*)(base + H_DIM) + tid;
#pragma unroll 4
    for (int s = 0; s < nt; s++) {
        float2 v = b2[(size_t)s * (H_DIM / 2)];
        float pw = prob[s];
        acc.x += pw * v.x; acc.y += pw * v.y;
    }
    ((float2*)(ctx + (size_t)i * H_DIM))[tid] = acc;
}

// --------------------------- gate + residual + LN ---------------------------
__global__ __launch_bounds__(256) void gate_ln_kernel(
    const float* __restrict__ ori, const float* __restrict__ ctx,
    const float* __restrict__ Wg, const float* __restrict__ bg,
    const float* __restrict__ ls, const float* __restrict__ lb,
    float* __restrict__ out, int gate_from_ctx)
{
    const int i = blockIdx.x;
    __shared__ float v[H_DIM];
    __shared__ float red[256];
    const int tid = threadIdx.x;
    const float* orow = ori + (size_t)i * H_DIM;
    const float* crow = ctx + (size_t)i * H_DIM;

    float p = 0.f;
    for (int c = tid; c < H_DIM; c += 256) {
        float gs = gate_from_ctx ? crow[c] : orow[c];
        p += gs * Wg[c];
    }
    red[tid] = p; __syncthreads();
    for (int o = 128; o; o >>= 1) { if (tid < o) red[tid] += red[tid + o]; __syncthreads(); }
    float gate = tanhf(red[0] + bg[0]);
    __syncthreads();

    float sum = 0.f;
    for (int c = tid; c < H_DIM; c += 256) {
        float val = orow[c] * gate + crow[c];
        v[c] = val; sum += val;
    }
    red[tid] = sum; __syncthreads();
    for (int o = 128; o; o >>= 1) { if (tid < o) red[tid] += red[tid + o]; __syncthreads(); }
    float mean = red[0] / (float)H_DIM;
    __syncthreads();

    float var = 0.f;
    for (int c = tid; c < H_DIM; c += 256) { float d = v[c] - mean; var += d * d; }
    red[tid] = var; __syncthreads();
    for (int o = 128; o; o >>= 1) { if (tid < o) red[tid] += red[tid + o]; __syncthreads(); }
    float rstd = rsqrtf(red[0] / (float)H_DIM + 1e-5f);

    for (int c = tid; c < H_DIM; c += 256)
        out[(size_t)i * H_DIM + c] = (v[c] - mean) * rstd * ls[c] + lb[c];
}

// -------------------------------- final score -------------------------------
__global__ __launch_bounds__(256) void score_kernel(
    const float* __restrict__ mti, const float* __restrict__ eti,
    const float* __restrict__ mit, const float* __restrict__ eit,
    float* __restrict__ out)
{
    __shared__ float As[8][64];
    __shared__ float Bs[8][64];
    const int n0 = blockIdx.x * 64;
    const int b0 = blockIdx.y * 64;
    const int tid = threadIdx.x;
    const int tx = tid & 15, ty = tid >> 4;
    const int lrow = tid >> 2, lcol = (tid & 3) * 2;

    float acc[4][4];
#pragma unroll
    for (int q = 0; q < 4; q++)
#pragma unroll
        for (int r = 0; r < 4; r++) acc[q][r] = 0.f;

#pragma unroll
    for (int pass = 0; pass < 2; pass++) {
        const float* A = pass ? mit : mti;
        const float* B = pass ? eit : eti;
        for (int k0 = 0; k0 < H_DIM; k0 += 8) {
            float2 av = *(const float2*)(A + (size_t)(b0 + lrow) * H_DIM + k0 + lcol);
            As[lcol][lrow] = av.x; As[lcol + 1][lrow] = av.y;
            float2 bv = *(const float2*)(B + (size_t)(n0 + lrow) * H_DIM + k0 + lcol);
            Bs[lcol][lrow] = bv.x; Bs[lcol + 1][lrow] = bv.y;
            __syncthreads();
#pragma unroll
            for (int k = 0; k < 8; k++) {
                float a[4], b[4];
#pragma unroll
                for (int q = 0; q < 4; q++) a[q] = As[k][ty * 4 + q];
#pragma unroll
                for (int q = 0; q < 4; q++) b[q] = Bs[k][tx * 4 + q];
#pragma unroll
                for (int q = 0; q < 4; q++)
#pragma unroll
                    for (int r = 0; r < 4; r++) acc[q][r] += a[q] * b[r];
            }
            __syncthreads();
        }
    }
#pragma unroll
    for (int q = 0; q < 4; q++)
#pragma unroll
        for (int r = 0; r < 4; r++)
            out[(size_t)(b0 + ty * 4 + q) * N_ENT + (n0 + tx * 4 + r)] = 0.5f * acc[q][r];
}

// ---------------------------------- launch ----------------------------------
extern "C" void kernel_launch(void* const* d_in, const int* in_sizes, int n_in,
                              void* d_out, int out_size)
{
    const float* etc_in = (const float*)d_in[0];
    const float* ett_in = (const float*)d_in[1];
    const float* mtc_in = (const float*)d_in[2];
    const float* mtt_in = (const float*)d_in[3];
    const float* eic_in = (const float*)d_in[4];
    const float* eit_in = (const float*)d_in[5];
    const float* mic_in = (const float*)d_in[6];
    const float* mit_in = (const float*)d_in[7];
    const float* W_text = (const float*)d_in[8];
    const float* b_text = (const float*)d_in[9];
    const float* W_img  = (const float*)d_in[10];
    const float* b_img  = (const float*)d_in[11];
    const float* W_gate = (const float*)d_in[12];
    const float* b_gate = (const float*)d_in[13];
    const float* ln_s   = (const float*)d_in[14];
    const float* ln_b   = (const float*)d_in[15];
    const float* W_rout = (const float*)d_in[16];
    const float* b_rout = (const float*)d_in[17];
    const float* W_exp  = (const float*)d_in[18];
    const float* b_exp  = (const float*)d_in[19];
    float* out = (float*)d_out;

    float *p_etc, *p_eic, *p_mtc, *p_mic, *p_ett, *p_eit, *p_mtt, *p_mit;
    float *p_etim, *p_mtim, *p_eitm, *p_mitm;
    float *p_ctx0, *p_ctx1, *p_ctx2, *p_ctx3;
    float *p_feti, *p_fmti, *p_feit, *p_fmit;
    float *p_wct, *p_wci, *p_bt;
    int2* p_eidx; float2* p_ew;
    cudaGetSymbolAddress((void**)&p_etc, g_etc);
    cudaGetSymbolAddress((void**)&p_eic, g_eic);
    cudaGetSymbolAddress((void**)&p_mtc, g_mtc);
    cudaGetSymbolAddress((void**)&p_mic, g_mic);
    cudaGetSymbolAddress((void**)&p_ett, g_ett);
    cudaGetSymbolAddress((void**)&p_eit, g_eit);
    cudaGetSymbolAddress((void**)&p_mtt, g_mtt);
    cudaGetSymbolAddress((void**)&p_mit, g_mit);
    cudaGetSymbolAddress((void**)&p_etim, g_eti_m);
    cudaGetSymbolAddress((void**)&p_mtim, g_mti_m);
    cudaGetSymbolAddress((void**)&p_eitm, g_eit_m);
    cudaGetSymbolAddress((void**)&p_mitm, g_mit_m);
    cudaGetSymbolAddress((void**)&p_ctx0, g_ctx0);
    cudaGetSymbolAddress((void**)&p_ctx1, g_ctx1);
    cudaGetSymbolAddress((void**)&p_ctx2, g_ctx2);
    cudaGetSymbolAddress((void**)&p_ctx3, g_ctx3);
    cudaGetSymbolAddress((void**)&p_feti, g_fe_ti);
    cudaGetSymbolAddress((void**)&p_fmti, g_fm_ti);
    cudaGetSymbolAddress((void**)&p_feit, g_fe_it);
    cudaGetSymbolAddress((void**)&p_fmit, g_fm_it);
    cudaGetSymbolAddress((void**)&p_wct, g_wc_text);
    cudaGetSymbolAddress((void**)&p_wci, g_wc_img);
    cudaGetSymbolAddress((void**)&p_bt, g_bterm);
    cudaGetSymbolAddress((void**)&p_eidx, g_eidx);
    cudaGetSymbolAddress((void**)&p_ew,   g_ew);

    dim3 blk(256);
    dim3 blkg(128);

    // 1-2: router weight folding
    combine_w_kernel<<<(D_IN * N_EXP + 255) / 256, blk>>>(W_text, W_img, W_rout, p_wct, p_wci);
    bterm_kernel<<<1, 32>>>(b_text, b_img, W_rout, b_rout, p_bt);

    // 3: first big router
    router2_kernel<<<N_ENT, blk>>>(eic_in, ett_in, T_TOK, p_wci, p_wct, p_bt,
                                   p_eidx + 0 * N_ENT, p_ew + 0 * N_ENT);

    // 4: big ett projection — positioned for ncu capture
    proj_tc<<<dim3(N_ENT * T_TOK / 128, 4), blkg>>>(ett_in, W_text, b_text, p_ett, N_ENT * T_TOK);

    // remaining routers
    router2_kernel<<<BATCH, blk>>>(mic_in, mtt_in, T_TOK, p_wci, p_wct, p_bt,
                                   p_eidx + 1 * N_ENT, p_ew + 1 * N_ENT);
    router2_kernel<<<N_ENT, blk>>>(etc_in, eit_in, P_TOK, p_wct, p_wci, p_bt + N_EXP,
                                   p_eidx + 2 * N_ENT, p_ew + 2 * N_ENT);
    router2_kernel<<<BATCH, blk>>>(mtc_in, mit_in, P_TOK, p_wct, p_wci, p_bt + N_EXP,
                                   p_eidx + 3 * N_ENT, p_ew + 3 * N_ENT);

    // remaining projections
    proj_tc<<<dim3(N_ENT / 128, 4), blkg>>>(etc_in, W_text, b_text, p_etc, N_ENT);
    proj_tc<<<dim3(BATCH / 128, 4), blkg>>>(mtc_in, W_text, b_text, p_mtc, BATCH);
    proj_tc<<<dim3(BATCH * T_TOK / 128, 4), blkg>>>(mtt_in, W_text, b_text, p_mtt, BATCH * T_TOK);
    proj_tc<<<dim3(N_ENT / 128, 4), blkg>>>(eic_in, W_img, b_img, p_eic, N_ENT);
    proj_tc<<<dim3(N_ENT * P_TOK / 128, 4), blkg>>>(eit_in, W_img, b_img, p_eit, N_ENT * P_TOK);
    proj_tc<<<dim3(BATCH / 128, 4), blkg>>>(mic_in, W_img, b_img, p_mic, BATCH);
    proj_tc<<<dim3(BATCH * P_TOK / 128, 4), blkg>>>(mit_in, W_img, b_img, p_mit, BATCH * P_TOK);

    // MoE GEMMs (combined expert pair, bf16x3)
    moe2_tc<<<dim3(2, 1, N_ENT), blkg>>>(p_etc, p_eit, W_exp, b_exp,
                                         p_eidx + 0 * N_ENT, p_ew + 0 * N_ENT, p_etim);
    moe2_tc<<<dim3(2, 1, BATCH), blkg>>>(p_mtc, p_mit, W_exp, b_exp,
                                         p_eidx + 1 * N_ENT, p_ew + 1 * N_ENT, p_mtim);
    moe3_tc<<<dim3(4, 1, N_ENT), blkg>>>(p_eic, p_ett, W_exp, b_exp,
                                         p_eidx + 2 * N_ENT, p_ew + 2 * N_ENT, p_eitm);
    moe3_tc<<<dim3(4, 1, BATCH), blkg>>>(p_mic, p_mtt, W_exp, b_exp,
                                         p_eidx + 3 * N_ENT, p_ew + 3 * N_ENT, p_mitm);

    // cross attention
    cross_kernel<<<N_ENT, blk>>>(p_etim, 50, p_ctx0);
    cross_kernel<<<BATCH, blk>>>(p_mtim, 50, p_ctx1);
    cross_kernel<<<N_ENT, blk>>>(p_eitm, 65, p_ctx2);
    cross_kernel<<<BATCH, blk>>>(p_mitm, 65, p_ctx3);

    // gate + residual + LN
    gate_ln_kernel<<<N_ENT, blk>>>(p_etc, p_ctx0, W_gate, b_gate, ln_s, ln_b, p_feti, 1);
    gate_ln_kernel<<<BATCH, blk>>>(p_mtc, p_ctx1, W_gate, b_gate, ln_s, ln_b, p_fmti, 0);
    gate_ln_kernel<<<N_ENT, blk>>>(p_eic, p_ctx2, W_gate, b_gate, ln_s, ln_b, p_feit, 1);
    gate_ln_kernel<<<BATCH, blk>>>(p_mic, p_ctx3, W_gate, b_gate, ln_s, ln_b, p_fmit, 0);

    // final score
    score_kernel<<<dim3(N_ENT / 64, BATCH / 64), blk>>>(p_fmti, p_feti, p_fmit, p_feit, out);
}

// round 11
// speedup vs baseline: 1.3103x; 1.0079x over previous
#include <cuda_runtime.h>
#include <cuda_bf16.h>
#include <math.h>
#include <stdint.h>

#define N_ENT 1024
#define BATCH 128
#define T_TOK 64
#define P_TOK 49
#define D_IN 768
#define H_DIM 512
#define N_EXP 8
#define NKP (D_IN / 2)     // 384 k-pairs
#define WSP_SZ (NKP * H_DIM)

// ----------------------------- static scratch ------------------------------
__device__ float g_etc[N_ENT * H_DIM];
__device__ float g_eic[N_ENT * H_DIM];
__device__ float g_mtc[BATCH * H_DIM];
__device__ float g_mic[BATCH * H_DIM];
__device__ float g_ett[N_ENT * T_TOK * H_DIM];
__device__ float g_eit[N_ENT * P_TOK * H_DIM];
__device__ float g_mtt[BATCH * T_TOK * H_DIM];
__device__ float g_mit[BATCH * P_TOK * H_DIM];

__device__ float g_eti_m[N_ENT * 50 * H_DIM];
__device__ float g_mti_m[BATCH * 50 * H_DIM];
__device__ float g_eit_m[N_ENT * 65 * H_DIM];
__device__ float g_mit_m[BATCH * 65 * H_DIM];

__device__ int2   g_eidx[4][N_ENT];
__device__ float2 g_ew[4][N_ENT];

__device__ float g_ctx0[N_ENT * H_DIM];
__device__ float g_ctx1[BATCH * H_DIM];
__device__ float g_ctx2[N_ENT * H_DIM];
__device__ float g_ctx3[BATCH * H_DIM];

__device__ float g_fe_ti[N_ENT * H_DIM];
__device__ float g_fm_ti[BATCH * H_DIM];
__device__ float g_fe_it[N_ENT * H_DIM];
__device__ float g_fm_it[BATCH * H_DIM];

__device__ float g_wc_text[D_IN * N_EXP];
__device__ float g_wc_img[D_IN * N_EXP];
__device__ float g_bterm[2 * N_EXP];

// pre-split projection weights: packed bf16 pairs (k, k+1), [pair][n]
__device__ uint32_t g_wsp_h[2 * WSP_SZ];   // [0]=text, [1]=img
__device__ uint32_t g_wsp_l[2 * WSP_SZ];

// --------------------------- bf16 split helpers -----------------------------
__device__ __forceinline__ void split_bf16x2(float a, float b, uint32_t& h, uint32_t& l)
{
    __nv_bfloat162 hp = __floats2bfloat162_rn(a, b);
    float ra = a - __bfloat162float(hp.x);
    float rb = b - __bfloat162float(hp.y);
    __nv_bfloat162 lp = __floats2bfloat162_rn(ra, rb);
    h = *(uint32_t*)&hp;
    l = *(uint32_t*)&lp;
}

__device__ __forceinline__ void splitB4(float4 r0, float4 r1, uint4& h, uint4& l)
{
    split_bf16x2(r0.x, r1.x, h.x, l.x);
    split_bf16x2(r0.y, r1.y, h.y, l.y);
    split_bf16x2(r0.z, r1.z, h.z, l.z);
    split_bf16x2(r0.w, r1.w, h.w, l.w);
}

__device__ __forceinline__ void mma16(float* c, const uint32_t* a, const uint32_t* b)
{
    asm volatile(
        "mma.sync.aligned.m16n8k16.row.col.f32.bf16.bf16.f32 "
        "{%0,%1,%2,%3}, {%4,%5,%6,%7}, {%8,%9}, {%0,%1,%2,%3};"
        : "+f"(c[0]), "+f"(c[1]), "+f"(c[2]), "+f"(c[3])
        : "r"(a[0]), "r"(a[1]), "r"(a[2]), "r"(a[3]), "r"(b[0]), "r"(b[1]));
}

#define ASTRP 12
#define BSTRP 136
#define BSTRP2 264

// ----------------- proj (bf16x3): C[M,512]=A[M,768]@W+bias -----------------
// grid (4 col-tiles, M/128 row-tiles): col tiles adjacent -> A L2 reuse.
// W pre-split (bit-identical to in-kernel split).
__global__ __launch_bounds__(128, 2) void proj_tc(
    const float* __restrict__ A,
    const uint32_t* __restrict__ Wh, const uint32_t* __restrict__ Wl,
    const float* __restrict__ bias, float* __restrict__ C, int M)
{
    __shared__ uint32_t AsH[128 * ASTRP], AsL[128 * ASTRP];
    __shared__ uint32_t BsH[8 * BSTRP], BsL[8 * BSTRP];

    const int tid = threadIdx.x;
    const int row0 = blockIdx.y * 128;
    const int col0 = blockIdx.x * 128;
    const int warp = tid >> 5, lane = tid & 31;
    const int wm = warp >> 1, wn = warp & 1;
    const int gid = lane >> 2, tig = lane & 3;
    const int bk = tid >> 4;            // B pair-row 0..7
    const int nc = (tid & 15) * 8;      // B col group

    float acc[4][8][4];
#pragma unroll
    for (int a = 0; a < 4; a++)
#pragma unroll
        for (int b = 0; b < 8; b++)
#pragma unroll
            for (int c = 0; c < 4; c++) acc[a][b][c] = 0.f;

    const float* Arow = A + (size_t)(row0 + tid) * D_IN;

    for (int kb = 0; kb < D_IN / 16; kb++) {
        const int k0 = kb * 16;
        // ---- A: 16 k-values -> 8 packed pairs ----
#pragma unroll
        for (int q = 0; q < 4; q++) {
            float4 v = *(const float4*)(Arow + k0 + q * 4);
            uint32_t h0, l0, h1, l1;
            split_bf16x2(v.x, v.y, h0, l0);
            split_bf16x2(v.z, v.w, h1, l1);
            *(uint2*)&AsH[tid * ASTRP + q * 2] = make_uint2(h0, h1);
            *(uint2*)&AsL[tid * ASTRP + q * 2] = make_uint2(l0, l1);
        }
        // ---- B: pre-split pairs, direct copy to smem ----
        {
            size_t off = (size_t)(kb * 8 + bk) * H_DIM + col0 + nc;
            *(uint4*)&BsH[bk * BSTRP + nc]     = *(const uint4*)(Wh + off);
            *(uint4*)&BsH[bk * BSTRP + nc + 4] = *(const uint4*)(Wh + off + 4);
            *(uint4*)&BsL[bk * BSTRP + nc]     = *(const uint4*)(Wl + off);
            *(uint4*)&BsL[bk * BSTRP + nc + 4] = *(const uint4*)(Wl + off + 4);
        }
        __syncthreads();

        uint32_t ah[4][4], al[4][4], bh[8][2], bl[8][2];
#pragma unroll
        for (int mt = 0; mt < 4; mt++) {
            int r = (wm * 64 + mt * 16 + gid) * ASTRP;
            ah[mt][0] = AsH[r + tig];     ah[mt][1] = AsH[r + 8 * ASTRP + tig];
            ah[mt][2] = AsH[r + tig + 4]; ah[mt][3] = AsH[r + 8 * ASTRP + tig + 4];
            al[mt][0] = AsL[r + tig];     al[mt][1] = AsL[r + 8 * ASTRP + tig];
            al[mt][2] = AsL[r + tig + 4]; al[mt][3] = AsL[r + 8 * ASTRP + tig + 4];
        }
#pragma unroll
        for (int nt = 0; nt < 8; nt++) {
            int c = wn * 64 + nt * 8 + gid;
            bh[nt][0] = BsH[tig * BSTRP + c]; bh[nt][1] = BsH[(tig + 4) * BSTRP + c];
            bl[nt][0] = BsL[tig * BSTRP + c]; bl[nt][1] = BsL[(tig + 4) * BSTRP + c];
        }
#pragma unroll
        for (int mt = 0; mt < 4; mt++)
#pragma unroll
            for (int nt = 0; nt < 8; nt++) mma16(acc[mt][nt], ah[mt], bh[nt]);
#pragma unroll
        for (int mt = 0; mt < 4; mt++)
#pragma unroll
            for (int nt = 0; nt < 8; nt++) mma16(acc[mt][nt], ah[mt], bl[nt]);
#pragma unroll
        for (int mt = 0; mt < 4; mt++)
#pragma unroll
            for (int nt = 0; nt < 8; nt++) mma16(acc[mt][nt], al[mt], bh[nt]);
        __syncthreads();
    }

#pragma unroll
    for (int mt = 0; mt < 4; mt++) {
        int m = row0 + wm * 64 + mt * 16 + gid;
#pragma unroll
        for (int nt = 0; nt < 8; nt++) {
            int n = col0 + wn * 64 + nt * 8 + tig * 2;
            float2 bv = *(const float2*)(bias + n);
            *(float2*)(C + (size_t)m * H_DIM + n) =
                make_float2(acc[mt][nt][0] + bv.x, acc[mt][nt][1] + bv.y);
            *(float2*)(C + (size_t)(m + 8) * H_DIM + n) =
                make_float2(acc[mt][nt][2] + bv.x, acc[mt][nt][3] + bv.y);
        }
    }
}

// -------- MoE S=50 (bf16x3): block 64x256, 4 warps of 64x64 ----------------
__global__ __launch_bounds__(128, 2) void moe2_tc(
    const float* __restrict__ cls, const float* __restrict__ tok,
    const float* __restrict__ We, const float* __restrict__ be,
    const int2* __restrict__ eidx, const float2* __restrict__ ew,
    float* __restrict__ out)
{
    const int S = 50;
    __shared__ uint32_t AsH[64 * ASTRP], AsL[64 * ASTRP];
    __shared__ uint32_t BsH[8 * BSTRP2], BsL[8 * BSTRP2];

    const int i = blockIdx.z;
    const int col0 = blockIdx.x * 256;
    const int2 e = eidx[i];
    const float2 w = ew[i];
    const float* W0 = We + (size_t)e.x * H_DIM * H_DIM;
    const float* W1 = We + (size_t)e.y * H_DIM * H_DIM;

    const int tid = threadIdx.x;
    const int warp = tid >> 5, lane = tid & 31;
    const int wn = warp;
    const int gid = lane >> 2, tig = lane & 3;
    const int bk = tid >> 4;
    const int nc = (tid & 15) * 16;
    const int arow = tid & 63, ahalf = tid >> 6;

    const float* rp = nullptr;
    if (arow < S)
        rp = (arow == 0) ? (cls + (size_t)i * H_DIM)
                         : (tok + ((size_t)i * (S - 1) + (arow - 1)) * H_DIM);

    float acc[4][8][4];
#pragma unroll
    for (int a = 0; a < 4; a++)
#pragma unroll
        for (int b = 0; b < 8; b++)
#pragma unroll
            for (int c = 0; c < 4; c++) acc[a][b][c] = 0.f;

    for (int kb = 0; kb < H_DIM / 16; kb++) {
        const int k0 = kb * 16;
#pragma unroll
        for (int q = 0; q < 2; q++) {
            float4 v = make_float4(0.f, 0.f, 0.f, 0.f);
            if (rp) v = *(const float4*)(rp + k0 + ahalf * 8 + q * 4);
            uint32_t h0, l0, h1, l1;
            split_bf16x2(v.x, v.y, h0, l0);
            split_bf16x2(v.z, v.w, h1, l1);
            *(uint2*)&AsH[arow * ASTRP + ahalf * 4 + q * 2] = make_uint2(h0, h1);
            *(uint2*)&AsL[arow * ASTRP + ahalf * 4 + q * 2] = make_uint2(l0, l1);
        }
        {
            size_t o0 = (size_t)(k0 + 2 * bk) * H_DIM + col0 + nc;
#pragma unroll
            for (int q = 0; q < 4; q++) {
                float4 a0 = *(const float4*)(W0 + o0 + q * 4);
                float4 b0 = *(const float4*)(W1 + o0 + q * 4);
                float4 a1 = *(const float4*)(W0 + o0 + H_DIM + q * 4);
                float4 b1 = *(const float4*)(W1 + o0 + H_DIM + q * 4);
                float4 r0 = make_float4(w.x * a0.x + w.y * b0.x, w.x * a0.y + w.y * b0.y,
                                        w.x * a0.z + w.y * b0.z, w.x * a0.w + w.y * b0.w);
                float4 r1 = make_float4(w.x * a1.x + w.y * b1.x, w.x * a1.y + w.y * b1.y,
                                        w.x * a1.z + w.y * b1.z, w.x * a1.w + w.y * b1.w);
                uint4 h, l;
                splitB4(r0, r1, h, l);
                *(uint4*)&BsH[bk * BSTRP2 + nc + q * 4] = h;
                *(uint4*)&BsL[bk * BSTRP2 + nc + q * 4] = l;
            }
        }
        __syncthreads();

        uint32_t ah[4][4], al[4][4], bh[8][2], bl[8][2];
#pragma unroll
        for (int mt = 0; mt < 4; mt++) {
            int r = (mt * 16 + gid) * ASTRP;
            ah[mt][0] = AsH[r + tig];     ah[mt][1] = AsH[r + 8 * ASTRP + tig];
            ah[mt][2] = AsH[r + tig + 4]; ah[mt][3] = AsH[r + 8 * ASTRP + tig + 4];
            al[mt][0] = AsL[r + tig];     al[mt][1] = AsL[r + 8 * ASTRP + tig];
            al[mt][2] = AsL[r + tig + 4]; al[mt][3] = AsL[r + 8 * ASTRP + tig + 4];
        }
#pragma unroll
        for (int nt = 0; nt < 8; nt++) {
            int c = wn * 64 + nt * 8 + gid;
            bh[nt][0] = BsH[tig * BSTRP2 + c]; bh[nt][1] = BsH[(tig + 4) * BSTRP2 + c];
            bl[nt][0] = BsL[tig * BSTRP2 + c]; bl[nt][1] = BsL[(tig + 4) * BSTRP2 + c];
        }
#pragma unroll
        for (int mt = 0; mt < 4; mt++)
#pragma unroll
            for (int nt = 0; nt < 8; nt++) mma16(acc[mt][nt], ah[mt], bh[nt]);
#pragma unroll
        for (int mt = 0; mt < 4; mt++)
#pragma unroll
            for (int nt = 0; nt < 8; nt++) mma16(acc[mt][nt], ah[mt], bl[nt]);
#pragma unroll
        for (int mt = 0; mt < 4; mt++)
#pragma unroll
            for (int nt = 0; nt < 8; nt++) mma16(acc[mt][nt], al[mt], bh[nt]);
        __syncthreads();
    }

#pragma unroll
    for (int mt = 0; mt < 4; mt++) {
        int t = mt * 16 + gid;
#pragma unroll
        for (int nt = 0; nt < 8; nt++) {
            int n = col0 + wn * 64 + nt * 8 + tig * 2;
            float b0 = w.x * be[e.x * H_DIM + n]     + w.y * be[e.y * H_DIM + n];
            float b1 = w.x * be[e.x * H_DIM + n + 1] + w.y * be[e.y * H_DIM + n + 1];
            if (t < S)
                *(float2*)(out + ((size_t)i * S + t) * H_DIM + n) =
                    make_float2(acc[mt][nt][0] + b0, acc[mt][nt][1] + b1);
            if (t + 8 < S)
                *(float2*)(out + ((size_t)i * S + t + 8) * H_DIM + n) =
                    make_float2(acc[mt][nt][2] + b0, acc[mt][nt][3] + b1);
        }
    }
}

// -------- MoE S=65 (bf16x3): block 96x128, 4 warps of 48x64 ----------------
__global__ __launch_bounds__(128, 2) void moe3_tc(
    const float* __restrict__ cls, const float* __restrict__ tok,
    const float* __restrict__ We, const float* __restrict__ be,
    const int2* __restrict__ eidx, const float2* __restrict__ ew,
    float* __restrict__ out)
{
    const int S = 65;
    __shared__ uint32_t AsH[96 * ASTRP], AsL[96 * ASTRP];
    __shared__ uint32_t BsH[8 * BSTRP], BsL[8 * BSTRP];

    const int i = blockIdx.z;
    const int col0 = blockIdx.x * 128;
    const int2 e = eidx[i];
    const float2 w = ew[i];
    const float* W0 = We + (size_t)e.x * H_DIM * H_DIM;
    const float* W1 = We + (size_t)e.y * H_DIM * H_DIM;

    const int tid = threadIdx.x;
    const int warp = tid >> 5, lane = tid & 31;
    const int wm = warp >> 1, wn = warp & 1;
    const int gid = lane >> 2, tig = lane & 3;
    const int bk = tid >> 4;
    const int nc = (tid & 15) * 8;

    const float* rp = nullptr;
    if (tid < S)
        rp = (tid == 0) ? (cls + (size_t)i * H_DIM)
                        : (tok + ((size_t)i * (S - 1) + (tid - 1)) * H_DIM);

    float acc[3][8][4];
#pragma unroll
    for (int a = 0; a < 3; a++)
#pragma unroll
        for (int b = 0; b < 8; b++)
#pragma unroll
            for (int c = 0; c < 4; c++) acc[a][b][c] = 0.f;

    for (int kb = 0; kb < H_DIM / 16; kb++) {
        const int k0 = kb * 16;
        if (tid < 96) {
#pragma unroll
            for (int q = 0; q < 4; q++) {
                float4 v = make_float4(0.f, 0.f, 0.f, 0.f);
                if (rp) v = *(const float4*)(rp + k0 + q * 4);
                uint32_t h0, l0, h1, l1;
                split_bf16x2(v.x, v.y, h0, l0);
                split_bf16x2(v.z, v.w, h1, l1);
                *(uint2*)&AsH[tid * ASTRP + q * 2] = make_uint2(h0, h1);
                *(uint2*)&AsL[tid * ASTRP + q * 2] = make_uint2(l0, l1);
            }
        }
        {
            size_t o0 = (size_t)(k0 + 2 * bk) * H_DIM + col0 + nc;
#pragma unroll
            for (int q = 0; q < 2; q++) {
                float4 a0 = *(const float4*)(W0 + o0 + q * 4);
                float4 b0 = *(const float4*)(W1 + o0 + q * 4);
                float4 a1 = *(const float4*)(W0 + o0 + H_DIM + q * 4);
                float4 b1 = *(const float4*)(W1 + o0 + H_DIM + q * 4);
                float4 r0 = make_float4(w.x * a0.x + w.y * b0.x, w.x * a0.y + w.y * b0.y,
                                        w.x * a0.z + w.y * b0.z, w.x * a0.w + w.y * b0.w);
                float4 r1 = make_float4(w.x * a1.x + w.y * b1.x, w.x * a1.y + w.y * b1.y,
                                        w.x * a1.z + w.y * b1.z, w.x * a1.w + w.y * b1.w);
                uint4 h, l;
                splitB4(r0, r1, h, l);
                *(uint4*)&BsH[bk * BSTRP + nc + q * 4] = h;
                *(uint4*)&BsL[bk * BSTRP + nc + q * 4] = l;
            }
        }
        __syncthreads();

        uint32_t ah[3][4], al[3][4], bh[8][2], bl[8][2];
#pragma unroll
        for (int mt = 0; mt < 3; mt++) {
            int r = (wm * 48 + mt * 16 + gid) * ASTRP;
            ah[mt][0] = AsH[r + tig];     ah[mt][1] = AsH[r + 8 * ASTRP + tig];
            ah[mt][2] = AsH[r + tig + 4]; ah[mt][3] = AsH[r + 8 * ASTRP + tig + 4];
            al[mt][0] = AsL[r + tig];     al[mt][1] = AsL[r + 8 * ASTRP + tig];
            al[mt][2] = AsL[r + tig + 4]; al[mt][3] = AsL[r + 8 * ASTRP + tig + 4];
        }
#pragma unroll
        for (int nt = 0; nt < 8; nt++) {
            int c = wn * 64 + nt * 8 + gid;
            bh[nt][0] = BsH[tig * BSTRP + c]; bh[nt][1] = BsH[(tig + 4) * BSTRP + c];
            bl[nt][0] = BsL[tig * BSTRP + c]; bl[nt][1] = BsL[(tig + 4) * BSTRP + c];
        }
#pragma unroll
        for (int mt = 0; mt < 3; mt++)
#pragma unroll
            for (int nt = 0; nt < 8; nt++) mma16(acc[mt][nt], ah[mt], bh[nt]);
#pragma unroll
        for (int mt = 0; mt < 3; mt++)
#pragma unroll
            for (int nt = 0; nt < 8; nt++) mma16(acc[mt][nt], ah[mt], bl[nt]);
#pragma unroll
        for (int mt = 0; mt < 3; mt++)
#pragma unroll
            for (int nt = 0; nt < 8; nt++) mma16(acc[mt][nt], al[mt], bh[nt]);
        __syncthreads();
    }

#pragma unroll
    for (int mt = 0; mt < 3; mt++) {
        int t = wm * 48 + mt * 16 + gid;
#pragma unroll
        for (int nt = 0; nt < 8; nt++) {
            int n = col0 + wn * 64 + nt * 8 + tig * 2;
            float b0 = w.x * be[e.x * H_DIM + n]     + w.y * be[e.y * H_DIM + n];
            float b1 = w.x * be[e.x * H_DIM + n + 1] + w.y * be[e.y * H_DIM + n + 1];
            if (t < S)
                *(float2*)(out + ((size_t)i * S + t) * H_DIM + n) =
                    make_float2(acc[mt][nt][0] + b0, acc[mt][nt][1] + b1);
            if (t + 8 < S)
                *(float2*)(out + ((size_t)i * S + t + 8) * H_DIM + n) =
                    make_float2(acc[mt][nt][2] + b0, acc[mt][nt][3] + b1);
        }
    }
}

// ------ router weight folding + projection-weight pre-split (one kernel) ----
__global__ void combine_w_kernel(const float* __restrict__ Wt, const float* __restrict__ Wi,
                                 const float* __restrict__ Wr,
                                 float* __restrict__ WcT, float* __restrict__ WcI,
                                 uint32_t* __restrict__ Wh, uint32_t* __restrict__ Wl)
{
    int idx = blockIdx.x * blockDim.x + threadIdx.x;
    // part 1: fold router weights (first 6144 threads)
    if (idx < D_IN * N_EXP) {
        int k = idx >> 3, e = idx & 7;
        float st = 0.f, si = 0.f;
        for (int h = 0; h < H_DIM; h++) {
            float wr = Wr[h * N_EXP + e];
            st += Wt[(size_t)k * H_DIM + h] * wr;
            si += Wi[(size_t)k * H_DIM + h] * wr;
        }
        WcT[idx] = st;
        WcI[idx] = si;
    }
    // part 2: pre-split W_text / W_img into packed bf16 pairs
    if (idx < 2 * WSP_SZ) {
        int which = idx / WSP_SZ;
        int rem = idx - which * WSP_SZ;
        int p = rem / H_DIM, n = rem - (rem / H_DIM) * H_DIM;
        const float* W = which ? Wi : Wt;
        float a = W[(size_t)(2 * p) * H_DIM + n];
        float b = W[(size_t)(2 * p + 1) * H_DIM + n];
        uint32_t h, l;
        split_bf16x2(a, b, h, l);
        Wh[idx] = h;
        Wl[idx] = l;
    }
}

__global__ void bterm_kernel(const float* __restrict__ bt, const float* __restrict__ bi,
                             const float* __restrict__ Wr, const float* __restrict__ br,
                             float* __restrict__ bterm)
{
    int e = threadIdx.x;
    if (e < N_EXP) {
        float sA = 0.f, sB = 0.f;
        for (int h = 0; h < H_DIM; h++) {
            float wr = Wr[h * N_EXP + e];
            sA += (bi[h] + 64.f * bt[h]) * wr;
            sB += (bt[h] + 49.f * bi[h]) * wr;
        }
        bterm[e]         = sA / 65.f + br[e];
        bterm[N_EXP + e] = sB / 50.f + br[e];
    }
}

// -------- router: stage1 bandwidth token-sum (float4), stage2 logits -------
__global__ __launch_bounds__(256) void router2_kernel(
    const float* __restrict__ cls, const float* __restrict__ tok, int Sm1,
    const float* __restrict__ WcCls, const float* __restrict__ WcTok,
    const float* __restrict__ bt,
    int2* __restrict__ eidx, float2* __restrict__ ew)
{
    const int i = blockIdx.x, tid = threadIdx.x;
    __shared__ float sumtok[D_IN];
    __shared__ float red[8][N_EXP];
    __shared__ float logits[N_EXP];

    if (tid < 192) {
        const float4* tp = (const float4*)(tok + (size_t)i * Sm1 * D_IN) + tid;
        float4 s0 = make_float4(0.f, 0.f, 0.f, 0.f), s1 = s0, s2 = s0, s3 = s0;
        int t = 0;
        for (; t + 4 <= Sm1; t += 4) {
            float4 a = tp[(size_t)(t + 0) * 192];
            float4 b = tp[(size_t)(t + 1) * 192];
            float4 c = tp[(size_t)(t + 2) * 192];
            float4 d = tp[(size_t)(t + 3) * 192];
            s0.x += a.x; s0.y += a.y; s0.z += a.z; s0.w += a.w;
            s1.x += b.x; s1.y += b.y; s1.z += b.z; s1.w += b.w;
            s2.x += c.x; s2.y += c.y; s2.z += c.z; s2.w += c.w;
            s3.x += d.x; s3.y += d.y; s3.z += d.z; s3.w += d.w;
        }
        for (; t < Sm1; t++) {
            float4 a = tp[(size_t)t * 192];
            s0.x += a.x; s0.y += a.y; s0.z += a.z; s0.w += a.w;
        }
        float4 s = make_float4(s0.x + s1.x + s2.x + s3.x, s0.y + s1.y + s2.y + s3.y,
                               s0.z + s1.z + s2.z + s3.z, s0.w + s1.w + s2.w + s3.w);
        *(float4*)&sumtok[tid * 4] = s;
    }
    __syncthreads();

    const int warp = tid >> 5, lane = tid & 31;
    {
        float part[N_EXP];
#pragma unroll
        for (int e = 0; e < N_EXP; e++) part[e] = 0.f;
        for (int c = tid; c < D_IN; c += 256) {
            float cl = cls[(size_t)i * D_IN + c];
            float s = sumtok[c];
#pragma unroll
            for (int e = 0; e < N_EXP; e++)
                part[e] += cl * WcCls[c * N_EXP + e] + s * WcTok[c * N_EXP + e];
        }
#pragma unroll
        for (int o = 16; o; o >>= 1)
#pragma unroll
            for (int e = 0; e < N_EXP; e++)
                part[e] += __shfl_down_sync(0xffffffffu, part[e], o);
        if (lane == 0)
#pragma unroll
            for (int e = 0; e < N_EXP; e++) red[warp][e] = part[e];
    }
    __syncthreads();
    if (tid < N_EXP) {
        float l = 0.f;
        for (int wq = 0; wq < 8; wq++) l += red[wq][tid];
        logits[tid] = l / (float)(Sm1 + 1) + bt[tid];
    }
    __syncthreads();
    if (tid == 0) {
        int b0 = 0;
        for (int e = 1; e < N_EXP; e++)
            if (logits[e] > logits[b0]) b0 = e;
        int b1 = (b0 == 0) ? 1 : 0;
        for (int e = 0; e < N_EXP; e++)
            if (e != b0 && logits[e] > logits[b1]) b1 = e;
        float e1v = expf(logits[b1] - logits[b0]);
        float inv = 1.0f / (1.0f + e1v);
        eidx[i] = make_int2(b0, b1);
        ew[i] = make_float2(inv, e1v * inv);
    }
}

// ---------------------- cross attention (vectorized) -----------------------
__global__ __launch_bounds__(256) void cross_kernel(
    const float* __restrict__ moe_out, int S, float* __restrict__ ctx)
{
    const int i = blockIdx.x;
    __shared__ float4 cls4[H_DIM / 4];
    __shared__ float prob[64];
    const int tid = threadIdx.x;
    const float* base = moe_out + (size_t)i * S * H_DIM;

    if (tid < H_DIM / 4) cls4[tid] = ((const float4*)base)[tid];
    __syncthreads();

    const int nt = S - 1;
    const int warp = tid >> 5, lane = tid & 31;
    for (int s = warp; s < nt; s += 8) {
        const float4* tr = (const float4*)(base + (size_t)(s + 1) * H_DIM);
        float p = 0.f;
#pragma unroll
        for (int q = 0; q < 4; q++) {
            float4 a = cls4[lane + 32 * q];
            float4 b = tr[lane + 32 * q];
            p += a.x * b.x + a.y * b.y + a.z * b.z + a.w * b.w;
        }
#pragma unroll
        for (int o = 16; o; o >>= 1) p += __shfl_down_sync(0xffffffffu, p, o);
        if (lane == 0) prob[s] = p;
    }
    __syncthreads();

    if (tid == 0) {
        float mx = -1e30f;
        for (int s = 0; s < nt; s++) mx = fmaxf(mx, prob[s]);
        float sum = 0.f;
        for (int s = 0; s < nt; s++) { float e = expf(prob[s] - mx); prob[s] = e; sum += e; }
        float inv = 1.0f / sum;
        for (int s = 0; s < nt; s++) prob[s] *= inv;
    }
    __syncthreads();

    float2 acc = make_float2(0.f, 0.f);
    const float2* b2 = (const float2*)(base + H_DIM) + tid;
#pragma unroll 4
    for (int s = 0; s < nt; s++) {
        float2 v = b2[(size_t)s * (H_DIM / 2)];
        float pw = prob[s];
        acc.x += pw * v.x; acc.y += pw * v.y;
    }
    ((float2*)(ctx + (size_t)i * H_DIM))[tid] = acc;
}

// --------------------------- gate + residual + LN ---------------------------
__global__ __launch_bounds__(256) void gate_ln_kernel(
    const float* __restrict__ ori, const float* __restrict__ ctx,
    const float* __restrict__ Wg, const float* __restrict__ bg,
    const float* __restrict__ ls, const float* __restrict__ lb,
    float* __restrict__ out, int gate_from_ctx)
{
    const int i = blockIdx.x;
    __shared__ float v[H_DIM];
    __shared__ float red[256];
    const int tid = threadIdx.x;
    const float* orow = ori + (size_t)i * H_DIM;
    const float* crow = ctx + (size_t)i * H_DIM;

    float p = 0.f;
    for (int c = tid; c < H_DIM; c += 256) {
        float gs = gate_from_ctx ? crow[c] : orow[c];
        p += gs * Wg[c];
    }
    red[tid] = p; __syncthreads();
    for (int o = 128; o; o >>= 1) { if (tid < o) red[tid] += red[tid + o]; __syncthreads(); }
    float gate = tanhf(red[0] + bg[0]);
    __syncthreads();

    float sum = 0.f;
    for (int c = tid; c < H_DIM; c += 256) {
        float val = orow[c] * gate + crow[c];
        v[c] = val; sum += val;
    }
    red[tid] = sum; __syncthreads();
    for (int o = 128; o; o >>= 1) { if (tid < o) red[tid] += red[tid + o]; __syncthreads(); }
    float mean = red[0] / (float)H_DIM;
    __syncthreads();

    float var = 0.f;
    for (int c = tid; c < H_DIM; c += 256) { float d = v[c] - mean; var += d * d; }
    red[tid] = var; __syncthreads();
    for (int o = 128; o; o >>= 1) { if (tid < o) red[tid] += red[tid + o]; __syncthreads(); }
    float rstd = rsqrtf(red[0] / (float)H_DIM + 1e-5f);

    for (int c = tid; c < H_DIM; c += 256)
        out[(size_t)i * H_DIM + c] = (v[c] - mean) * rstd * ls[c] + lb[c];
}

// -------------------------------- final score -------------------------------
__global__ __launch_bounds__(256) void score_kernel(
    const float* __restrict__ mti, const float* __restrict__ eti,
    const float* __restrict__ mit, const float* __restrict__ eit,
    float* __restrict__ out)
{
    __shared__ float As[8][64];
    __shared__ float Bs[8][64];
    const int n0 = blockIdx.x * 64;
    const int b0 = blockIdx.y * 64;
    const int tid = threadIdx.x;
    const int tx = tid & 15, ty = tid >> 4;
    const int lrow = tid >> 2, lcol = (tid & 3) * 2;

    float acc[4][4];
#pragma unroll
    for (int q = 0; q < 4; q++)
#pragma unroll
        for (int r = 0; r < 4; r++) acc[q][r] = 0.f;

#pragma unroll
    for (int pass = 0; pass < 2; pass++) {
        const float* A = pass ? mit : mti;
        const float* B = pass ? eit : eti;
        for (int k0 = 0; k0 < H_DIM; k0 += 8) {
            float2 av = *(const float2*)(A + (size_t)(b0 + lrow) * H_DIM + k0 + lcol);
            As[lcol][lrow] = av.x; As[lcol + 1][lrow] = av.y;
            float2 bv = *(const float2*)(B + (size_t)(n0 + lrow) * H_DIM + k0 + lcol);
            Bs[lcol][lrow] = bv.x; Bs[lcol + 1][lrow] = bv.y;
            __syncthreads();
#pragma unroll
            for (int k = 0; k < 8; k++) {
                float a[4], b[4];
#pragma unroll
                for (int q = 0; q < 4; q++) a[q] = As[k][ty * 4 + q];
#pragma unroll
                for (int q = 0; q < 4; q++) b[q] = Bs[k][tx * 4 + q];
#pragma unroll
                for (int q = 0; q < 4; q++)
#pragma unroll
                    for (int r = 0; r < 4; r++) acc[q][r] += a[q] * b[r];
            }
            __syncthreads();
        }
    }
#pragma unroll
    for (int q = 0; q < 4; q++)
#pragma unroll
        for (int r = 0; r < 4; r++)
            out[(size_t)(b0 + ty * 4 + q) * N_ENT + (n0 + tx * 4 + r)] = 0.5f * acc[q][r];
}

// ---------------------------------- launch ----------------------------------
extern "C" void kernel_launch(void* const* d_in, const int* in_sizes, int n_in,
                              void* d_out, int out_size)
{
    const float* etc_in = (const float*)d_in[0];
    const float* ett_in = (const float*)d_in[1];
    const float* mtc_in = (const float*)d_in[2];
    const float* mtt_in = (const float*)d_in[3];
    const float* eic_in = (const float*)d_in[4];
    const float* eit_in = (const float*)d_in[5];
    const float* mic_in = (const float*)d_in[6];
    const float* mit_in = (const float*)d_in[7];
    const float* W_text = (const float*)d_in[8];
    const float* b_text = (const float*)d_in[9];
    const float* W_img  = (const float*)d_in[10];
    const float* b_img  = (const float*)d_in[11];
    const float* W_gate = (const float*)d_in[12];
    const float* b_gate = (const float*)d_in[13];
    const float* ln_s   = (const float*)d_in[14];
    const float* ln_b   = (const float*)d_in[15];
    const float* W_rout = (const float*)d_in[16];
    const float* b_rout = (const float*)d_in[17];
    const float* W_exp  = (const float*)d_in[18];
    const float* b_exp  = (const float*)d_in[19];
    float* out = (float*)d_out;

    float *p_etc, *p_eic, *p_mtc, *p_mic, *p_ett, *p_eit, *p_mtt, *p_mit;
    float *p_etim, *p_mtim, *p_eitm, *p_mitm;
    float *p_ctx0, *p_ctx1, *p_ctx2, *p_ctx3;
    float *p_feti, *p_fmti, *p_feit, *p_fmit;
    float *p_wct, *p_wci, *p_bt;
    uint32_t *p_wh, *p_wl;
    int2* p_eidx; float2* p_ew;
    cudaGetSymbolAddress((void**)&p_etc, g_etc);
    cudaGetSymbolAddress((void**)&p_eic, g_eic);
    cudaGetSymbolAddress((void**)&p_mtc, g_mtc);
    cudaGetSymbolAddress((void**)&p_mic, g_mic);
    cudaGetSymbolAddress((void**)&p_ett, g_ett);
    cudaGetSymbolAddress((void**)&p_eit, g_eit);
    cudaGetSymbolAddress((void**)&p_mtt, g_mtt);
    cudaGetSymbolAddress((void**)&p_mit, g_mit);
    cudaGetSymbolAddress((void**)&p_etim, g_eti_m);
    cudaGetSymbolAddress((void**)&p_mtim, g_mti_m);
    cudaGetSymbolAddress((void**)&p_eitm, g_eit_m);
    cudaGetSymbolAddress((void**)&p_mitm, g_mit_m);
    cudaGetSymbolAddress((void**)&p_ctx0, g_ctx0);
    cudaGetSymbolAddress((void**)&p_ctx1, g_ctx1);
    cudaGetSymbolAddress((void**)&p_ctx2, g_ctx2);
    cudaGetSymbolAddress((void**)&p_ctx3, g_ctx3);
    cudaGetSymbolAddress((void**)&p_feti, g_fe_ti);
    cudaGetSymbolAddress((void**)&p_fmti, g_fm_ti);
    cudaGetSymbolAddress((void**)&p_feit, g_fe_it);
    cudaGetSymbolAddress((void**)&p_fmit, g_fm_it);
    cudaGetSymbolAddress((void**)&p_wct, g_wc_text);
    cudaGetSymbolAddress((void**)&p_wci, g_wc_img);
    cudaGetSymbolAddress((void**)&p_bt, g_bterm);
    cudaGetSymbolAddress((void**)&p_wh, g_wsp_h);
    cudaGetSymbolAddress((void**)&p_wl, g_wsp_l);
    cudaGetSymbolAddress((void**)&p_eidx, g_eidx);
    cudaGetSymbolAddress((void**)&p_ew,   g_ew);

    dim3 blk(256);
    dim3 blkg(128);

    // 1: router weight folding + projection weight pre-split (one kernel)
    combine_w_kernel<<<(2 * WSP_SZ + 255) / 256, blk>>>(W_text, W_img, W_rout,
                                                        p_wct, p_wci, p_wh, p_wl);
    // 2: bias terms
    bterm_kernel<<<1, 32>>>(b_text, b_img, W_rout, b_rout, p_bt);

    // 3: first big router
    router2_kernel<<<N_ENT, blk>>>(eic_in, ett_in, T_TOK, p_wci, p_wct, p_bt,
                                   p_eidx + 0 * N_ENT, p_ew + 0 * N_ENT);

    // 4: big ett projection — positioned for ncu capture
    proj_tc<<<dim3(4, N_ENT * T_TOK / 128), blkg>>>(ett_in, p_wh, p_wl, b_text, p_ett, N_ENT * T_TOK);

    // remaining routers
    router2_kernel<<<BATCH, blk>>>(mic_in, mtt_in, T_TOK, p_wci, p_wct, p_bt,
                                   p_eidx + 1 * N_ENT, p_ew + 1 * N_ENT);
    router2_kernel<<<N_ENT, blk>>>(etc_in, eit_in, P_TOK, p_wct, p_wci, p_bt + N_EXP,
                                   p_eidx + 2 * N_ENT, p_ew + 2 * N_ENT);
    router2_kernel<<<BATCH, blk>>>(mtc_in, mit_in, P_TOK, p_wct, p_wci, p_bt + N_EXP,
                                   p_eidx + 3 * N_ENT, p_ew + 3 * N_ENT);

    // remaining projections (text -> offset 0, img -> offset WSP_SZ)
    proj_tc<<<dim3(4, N_ENT / 128), blkg>>>(etc_in, p_wh, p_wl, b_text, p_etc, N_ENT);
    proj_tc<<<dim3(4, BATCH / 128), blkg>>>(mtc_in, p_wh, p_wl, b_text, p_mtc, BATCH);
    proj_tc<<<dim3(4, BATCH * T_TOK / 128), blkg>>>(mtt_in, p_wh, p_wl, b_text, p_mtt, BATCH * T_TOK);
    proj_tc<<<dim3(4, N_ENT / 128), blkg>>>(eic_in, p_wh + WSP_SZ, p_wl + WSP_SZ, b_img, p_eic, N_ENT);
    proj_tc<<<dim3(4, N_ENT * P_TOK / 128), blkg>>>(eit_in, p_wh + WSP_SZ, p_wl + WSP_SZ, b_img, p_eit, N_ENT * P_TOK);
    proj_tc<<<dim3(4, BATCH / 128), blkg>>>(mic_in, p_wh + WSP_SZ, p_wl + WSP_SZ, b_img, p_mic, BATCH);
    proj_tc<<<dim3(4, BATCH * P_TOK / 128), blkg>>>(mit_in, p_wh + WSP_SZ, p_wl + WSP_SZ, b_img, p_mit, BATCH * P_TOK);

    // MoE GEMMs (combined expert pair, bf16x3)
    moe2_tc<<<dim3(2, 1, N_ENT), blkg>>>(p_etc, p_eit, W_exp, b_exp,
                                         p_eidx + 0 * N_ENT, p_ew + 0 * N_ENT, p_etim);
    moe2_tc<<<dim3(2, 1, BATCH), blkg>>>(p_mtc, p_mit, W_exp, b_exp,
                                         p_eidx + 1 * N_ENT, p_ew + 1 * N_ENT, p_mtim);
    moe3_tc<<<dim3(4, 1, N_ENT), blkg>>>(p_eic, p_ett, W_exp, b_exp,
                                         p_eidx + 2 * N_ENT, p_ew + 2 * N_ENT, p_eitm);
    moe3_tc<<<dim3(4, 1, BATCH), blkg>>>(p_mic, p_mtt, W_exp, b_exp,
                                         p_eidx + 3 * N_ENT, p_ew + 3 * N_ENT, p_mitm);

    // cross attention
    cross_kernel<<<N_ENT, blk>>>(p_etim, 50, p_ctx0);
    cross_kernel<<<BATCH, blk>>>(p_mtim, 50, p_ctx1);
    cross_kernel<<<N_ENT, blk>>>(p_eitm, 65, p_ctx2);
    cross_kernel<<<BATCH, blk>>>(p_mitm, 65, p_ctx3);

    // gate + residual + LN
    gate_ln_kernel<<<N_ENT, blk>>>(p_etc, p_ctx0, W_gate, b_gate, ln_s, ln_b, p_feti, 1);
    gate_ln_kernel<<<BATCH, blk>>>(p_mtc, p_ctx1, W_gate, b_gate, ln_s, ln_b, p_fmti, 0);
    gate_ln_kernel<<<N_ENT, blk>>>(p_eic, p_ctx2, W_gate, b_gate, ln_s, ln_b, p_feit, 1);
    gate_ln_kernel<<<BATCH, blk>>>(p_mic, p_ctx3, W_gate, b_gate, ln_s, ln_b, p_fmit, 0);

    // final score
    score_kernel<<<dim3(N_ENT / 64, BATCH / 64), blk>>>(p_fmti, p_feti, p_fmit, p_feit, out);
}

// round 13
// speedup vs baseline: 1.3170x; 1.0051x over previous
#include <cuda_runtime.h>
#include <cuda_bf16.h>
#include <math.h>
#include <stdint.h>

#define N_ENT 1024
#define BATCH 128
#define T_TOK 64
#define P_TOK 49
#define D_IN 768
#define H_DIM 512
#define N_EXP 8
#define NKP (D_IN / 2)
#define WSP_SZ (NKP * H_DIM)

// ----------------------------- static scratch ------------------------------
__device__ float g_etc[N_ENT * H_DIM];
__device__ float g_eic[N_ENT * H_DIM];
__device__ float g_mtc[BATCH * H_DIM];
__device__ float g_mic[BATCH * H_DIM];
__device__ float g_ett[N_ENT * T_TOK * H_DIM];
__device__ float g_eit[N_ENT * P_TOK * H_DIM];
__device__ float g_mtt[BATCH * T_TOK * H_DIM];
__device__ float g_mit[BATCH * P_TOK * H_DIM];

__device__ float g_eti_m[N_ENT * 50 * H_DIM];
__device__ float g_mti_m[BATCH * 50 * H_DIM];
__device__ float g_eit_m[N_ENT * 65 * H_DIM];
__device__ float g_mit_m[BATCH * 65 * H_DIM];

__device__ int2   g_eidx[4][N_ENT];
__device__ float2 g_ew[4][N_ENT];

__device__ float g_ctx0[N_ENT * H_DIM];
__device__ float g_ctx1[BATCH * H_DIM];
__device__ float g_ctx2[N_ENT * H_DIM];
__device__ float g_ctx3[BATCH * H_DIM];

__device__ float g_fe_ti[N_ENT * H_DIM];
__device__ float g_fm_ti[BATCH * H_DIM];
__device__ float g_fe_it[N_ENT * H_DIM];
__device__ float g_fm_it[BATCH * H_DIM];

__device__ float g_wc_text[D_IN * N_EXP];
__device__ float g_wc_img[D_IN * N_EXP];
__device__ float g_bterm[2 * N_EXP];

// pre-split projection weights: packed bf16 pairs (k, k+1), [pair][n]
__device__ uint32_t g_wsp_h[2 * WSP_SZ];
__device__ uint32_t g_wsp_l[2 * WSP_SZ];

// --------------------------- bf16 split helpers -----------------------------
__device__ __forceinline__ void split_bf16x2(float a, float b, uint32_t& h, uint32_t& l)
{
    __nv_bfloat162 hp = __floats2bfloat162_rn(a, b);
    float ra = a - __bfloat162float(hp.x);
    float rb = b - __bfloat162float(hp.y);
    __nv_bfloat162 lp = __floats2bfloat162_rn(ra, rb);
    h = *(uint32_t*)&hp;
    l = *(uint32_t*)&lp;
}

__device__ __forceinline__ void splitB4(float4 r0, float4 r1, uint4& h, uint4& l)
{
    split_bf16x2(r0.x, r1.x, h.x, l.x);
    split_bf16x2(r0.y, r1.y, h.y, l.y);
    split_bf16x2(r0.z, r1.z, h.z, l.z);
    split_bf16x2(r0.w, r1.w, h.w, l.w);
}

__device__ __forceinline__ void mma16(float* c, const uint32_t* a, const uint32_t* b)
{
    asm volatile(
        "mma.sync.aligned.m16n8k16.row.col.f32.bf16.bf16.f32 "
        "{%0,%1,%2,%3}, {%4,%5,%6,%7}, {%8,%9}, {%0,%1,%2,%3};"
        : "+f"(c[0]), "+f"(c[1]), "+f"(c[2]), "+f"(c[3])
        : "r"(a[0]), "r"(a[1]), "r"(a[2]), "r"(a[3]), "r"(b[0]), "r"(b[1]));
}

#define ASTRP 12
#define BSTRP 136
#define BSTRP2 264

// ----------------- proj (bf16x3): C[M,512]=A[M,768]@W+bias -----------------
// grid (4 col-tiles, M/128 row-tiles); W pre-split packed pairs.
__global__ __launch_bounds__(128, 2) void proj_tc(
    const float* __restrict__ A,
    const uint32_t* __restrict__ Wh, const uint32_t* __restrict__ Wl,
    const float* __restrict__ bias, float* __restrict__ C, int M)
{
    __shared__ uint32_t AsH[128 * ASTRP], AsL[128 * ASTRP];
    __shared__ uint32_t BsH[8 * BSTRP], BsL[8 * BSTRP];

    const int tid = threadIdx.x;
    const int row0 = blockIdx.y * 128;
    const int col0 = blockIdx.x * 128;
    const int warp = tid >> 5, lane = tid & 31;
    const int wm = warp >> 1, wn = warp & 1;
    const int gid = lane >> 2, tig = lane & 3;
    const int bk = tid >> 4;
    const int nc = (tid & 15) * 8;

    float acc[4][8][4];
#pragma unroll
    for (int a = 0; a < 4; a++)
#pragma unroll
        for (int b = 0; b < 8; b++)
#pragma unroll
            for (int c = 0; c < 4; c++) acc[a][b][c] = 0.f;

    const float* Arow = A + (size_t)(row0 + tid) * D_IN;

    for (int kb = 0; kb < D_IN / 16; kb++) {
        const int k0 = kb * 16;
#pragma unroll
        for (int q = 0; q < 4; q++) {
            float4 v = *(const float4*)(Arow + k0 + q * 4);
            uint32_t h0, l0, h1, l1;
            split_bf16x2(v.x, v.y, h0, l0);
            split_bf16x2(v.z, v.w, h1, l1);
            *(uint2*)&AsH[tid * ASTRP + q * 2] = make_uint2(h0, h1);
            *(uint2*)&AsL[tid * ASTRP + q * 2] = make_uint2(l0, l1);
        }
        {
            size_t off = (size_t)(kb * 8 + bk) * H_DIM + col0 + nc;
            *(uint4*)&BsH[bk * BSTRP + nc]     = *(const uint4*)(Wh + off);
            *(uint4*)&BsH[bk * BSTRP + nc + 4] = *(const uint4*)(Wh + off + 4);
            *(uint4*)&BsL[bk * BSTRP + nc]     = *(const uint4*)(Wl + off);
            *(uint4*)&BsL[bk * BSTRP + nc + 4] = *(const uint4*)(Wl + off + 4);
        }
        __syncthreads();

        uint32_t ah[4][4], al[4][4], bh[8][2], bl[8][2];
#pragma unroll
        for (int mt = 0; mt < 4; mt++) {
            int r = (wm * 64 + mt * 16 + gid) * ASTRP;
            ah[mt][0] = AsH[r + tig];     ah[mt][1] = AsH[r + 8 * ASTRP + tig];
            ah[mt][2] = AsH[r + tig + 4]; ah[mt][3] = AsH[r + 8 * ASTRP + tig + 4];
            al[mt][0] = AsL[r + tig];     al[mt][1] = AsL[r + 8 * ASTRP + tig];
            al[mt][2] = AsL[r + tig + 4]; al[mt][3] = AsL[r + 8 * ASTRP + tig + 4];
        }
#pragma unroll
        for (int nt = 0; nt < 8; nt++) {
            int c = wn * 64 + nt * 8 + gid;
            bh[nt][0] = BsH[tig * BSTRP + c]; bh[nt][1] = BsH[(tig + 4) * BSTRP + c];
            bl[nt][0] = BsL[tig * BSTRP + c]; bl[nt][1] = BsL[(tig + 4) * BSTRP + c];
        }
#pragma unroll
        for (int mt = 0; mt < 4; mt++)
#pragma unroll
            for (int nt = 0; nt < 8; nt++) mma16(acc[mt][nt], ah[mt], bh[nt]);
#pragma unroll
        for (int mt = 0; mt < 4; mt++)
#pragma unroll
            for (int nt = 0; nt < 8; nt++) mma16(acc[mt][nt], ah[mt], bl[nt]);
#pragma unroll
        for (int mt = 0; mt < 4; mt++)
#pragma unroll
            for (int nt = 0; nt < 8; nt++) mma16(acc[mt][nt], al[mt], bh[nt]);
        __syncthreads();
    }

#pragma unroll
    for (int mt = 0; mt < 4; mt++) {
        int m = row0 + wm * 64 + mt * 16 + gid;
#pragma unroll
        for (int nt = 0; nt < 8; nt++) {
            int n = col0 + wn * 64 + nt * 8 + tig * 2;
            float2 bv = *(const float2*)(bias + n);
            *(float2*)(C + (size_t)m * H_DIM + n) =
                make_float2(acc[mt][nt][0] + bv.x, acc[mt][nt][1] + bv.y);
            *(float2*)(C + (size_t)(m + 8) * H_DIM + n) =
                make_float2(acc[mt][nt][2] + bv.x, acc[mt][nt][3] + bv.y);
        }
    }
}

// -------- MoE S=50 (bf16x3): block 64x256, 4 warps of 64x64 ----------------
__global__ __launch_bounds__(128, 2) void moe2_tc(
    const float* __restrict__ cls, const float* __restrict__ tok,
    const float* __restrict__ We, const float* __restrict__ be,
    const int2* __restrict__ eidx, const float2* __restrict__ ew,
    float* __restrict__ out)
{
    const int S = 50;
    __shared__ uint32_t AsH[64 * ASTRP], AsL[64 * ASTRP];
    __shared__ uint32_t BsH[8 * BSTRP2], BsL[8 * BSTRP2];

    const int i = blockIdx.z;
    const int col0 = blockIdx.x * 256;
    const int2 e = eidx[i];
    const float2 w = ew[i];
    const float* W0 = We + (size_t)e.x * H_DIM * H_DIM;
    const float* W1 = We + (size_t)e.y * H_DIM * H_DIM;

    const int tid = threadIdx.x;
    const int warp = tid >> 5, lane = tid & 31;
    const int wn = warp;
    const int gid = lane >> 2, tig = lane & 3;
    const int bk = tid >> 4;
    const int nc = (tid & 15) * 16;
    const int arow = tid & 63, ahalf = tid >> 6;

    const float* rp = nullptr;
    if (arow < S)
        rp = (arow == 0) ? (cls + (size_t)i * H_DIM)
                         : (tok + ((size_t)i * (S - 1) + (arow - 1)) * H_DIM);

    float acc[4][8][4];
#pragma unroll
    for (int a = 0; a < 4; a++)
#pragma unroll
        for (int b = 0; b < 8; b++)
#pragma unroll
            for (int c = 0; c < 4; c++) acc[a][b][c] = 0.f;

    for (int kb = 0; kb < H_DIM / 16; kb++) {
        const int k0 = kb * 16;
#pragma unroll
        for (int q = 0; q < 2; q++) {
            float4 v = make_float4(0.f, 0.f, 0.f, 0.f);
            if (rp) v = *(const float4*)(rp + k0 + ahalf * 8 + q * 4);
            uint32_t h0, l0, h1, l1;
            split_bf16x2(v.x, v.y, h0, l0);
            split_bf16x2(v.z, v.w, h1, l1);
            *(uint2*)&AsH[arow * ASTRP + ahalf * 4 + q * 2] = make_uint2(h0, h1);
            *(uint2*)&AsL[arow * ASTRP + ahalf * 4 + q * 2] = make_uint2(l0, l1);
        }
        {
            size_t o0 = (size_t)(k0 + 2 * bk) * H_DIM + col0 + nc;
#pragma unroll
            for (int q = 0; q < 4; q++) {
                float4 a0 = *(const float4*)(W0 + o0 + q * 4);
                float4 b0 = *(const float4*)(W1 + o0 + q * 4);
                float4 a1 = *(const float4*)(W0 + o0 + H_DIM + q * 4);
                float4 b1 = *(const float4*)(W1 + o0 + H_DIM + q * 4);
                float4 r0 = make_float4(w.x * a0.x + w.y * b0.x, w.x * a0.y + w.y * b0.y,
                                        w.x * a0.z + w.y * b0.z, w.x * a0.w + w.y * b0.w);
                float4 r1 = make_float4(w.x * a1.x + w.y * b1.x, w.x * a1.y + w.y * b1.y,
                                        w.x * a1.z + w.y * b1.z, w.x * a1.w + w.y * b1.w);
                uint4 h, l;
                splitB4(r0, r1, h, l);
                *(uint4*)&BsH[bk * BSTRP2 + nc + q * 4] = h;
                *(uint4*)&BsL[bk * BSTRP2 + nc + q * 4] = l;
            }
        }
        __syncthreads();

        uint32_t ah[4][4], al[4][4], bh[8][2], bl[8][2];
#pragma unroll
        for (int mt = 0; mt < 4; mt++) {
            int r = (mt * 16 + gid) * ASTRP;
            ah[mt][0] = AsH[r + tig];     ah[mt][1] = AsH[r + 8 * ASTRP + tig];
            ah[mt][2] = AsH[r + tig + 4]; ah[mt][3] = AsH[r + 8 * ASTRP + tig + 4];
            al[mt][0] = AsL[r + tig];     al[mt][1] = AsL[r + 8 * ASTRP + tig];
            al[mt][2] = AsL[r + tig + 4]; al[mt][3] = AsL[r + 8 * ASTRP + tig + 4];
        }
#pragma unroll
        for (int nt = 0; nt < 8; nt++) {
            int c = wn * 64 + nt * 8 + gid;
            bh[nt][0] = BsH[tig * BSTRP2 + c]; bh[nt][1] = BsH[(tig + 4) * BSTRP2 + c];
            bl[nt][0] = BsL[tig * BSTRP2 + c]; bl[nt][1] = BsL[(tig + 4) * BSTRP2 + c];
        }
#pragma unroll
        for (int mt = 0; mt < 4; mt++)
#pragma unroll
            for (int nt = 0; nt < 8; nt++) mma16(acc[mt][nt], ah[mt], bh[nt]);
#pragma unroll
        for (int mt = 0; mt < 4; mt++)
#pragma unroll
            for (int nt = 0; nt < 8; nt++) mma16(acc[mt][nt], ah[mt], bl[nt]);
#pragma unroll
        for (int mt = 0; mt < 4; mt++)
#pragma unroll
            for (int nt = 0; nt < 8; nt++) mma16(acc[mt][nt], al[mt], bh[nt]);
        __syncthreads();
    }

#pragma unroll
    for (int mt = 0; mt < 4; mt++) {
        int t = mt * 16 + gid;
#pragma unroll
        for (int nt = 0; nt < 8; nt++) {
            int n = col0 + wn * 64 + nt * 8 + tig * 2;
            float b0 = w.x * be[e.x * H_DIM + n]     + w.y * be[e.y * H_DIM + n];
            float b1 = w.x * be[e.x * H_DIM + n + 1] + w.y * be[e.y * H_DIM + n + 1];
            if (t < S)
                *(float2*)(out + ((size_t)i * S + t) * H_DIM + n) =
                    make_float2(acc[mt][nt][0] + b0, acc[mt][nt][1] + b1);
            if (t + 8 < S)
                *(float2*)(out + ((size_t)i * S + t + 8) * H_DIM + n) =
                    make_float2(acc[mt][nt][2] + b0, acc[mt][nt][3] + b1);
        }
    }
}

// ---- MoE S=65 (bf16x3): block 80x128, 4 warps each 80x32 (BM 96->80) ------
__global__ __launch_bounds__(128, 2) void moe3_tc(
    const float* __restrict__ cls, const float* __restrict__ tok,
    const float* __restrict__ We, const float* __restrict__ be,
    const int2* __restrict__ eidx, const float2* __restrict__ ew,
    float* __restrict__ out)
{
    const int S = 65;
    __shared__ uint32_t AsH[80 * ASTRP], AsL[80 * ASTRP];
    __shared__ uint32_t BsH[8 * BSTRP], BsL[8 * BSTRP];

    const int i = blockIdx.z;
    const int col0 = blockIdx.x * 128;
    const int2 e = eidx[i];
    const float2 w = ew[i];
    const float* W0 = We + (size_t)e.x * H_DIM * H_DIM;
    const float* W1 = We + (size_t)e.y * H_DIM * H_DIM;

    const int tid = threadIdx.x;
    const int warp = tid >> 5, lane = tid & 31;
    const int wn = warp;                 // 4 warps across N (32 cols each)
    const int gid = lane >> 2, tig = lane & 3;
    const int bk = tid >> 4;
    const int nc = (tid & 15) * 8;

    const float* rp = nullptr;
    if (tid < S)
        rp = (tid == 0) ? (cls + (size_t)i * H_DIM)
                        : (tok + ((size_t)i * (S - 1) + (tid - 1)) * H_DIM);

    float acc[5][4][4];
#pragma unroll
    for (int a = 0; a < 5; a++)
#pragma unroll
        for (int b = 0; b < 4; b++)
#pragma unroll
            for (int c = 0; c < 4; c++) acc[a][b][c] = 0.f;

    for (int kb = 0; kb < H_DIM / 16; kb++) {
        const int k0 = kb * 16;
        if (tid < 80) {
#pragma unroll
            for (int q = 0; q < 4; q++) {
                float4 v = make_float4(0.f, 0.f, 0.f, 0.f);
                if (rp) v = *(const float4*)(rp + k0 + q * 4);
                uint32_t h0, l0, h1, l1;
                split_bf16x2(v.x, v.y, h0, l0);
                split_bf16x2(v.z, v.w, h1, l1);
                *(uint2*)&AsH[tid * ASTRP + q * 2] = make_uint2(h0, h1);
                *(uint2*)&AsL[tid * ASTRP + q * 2] = make_uint2(l0, l1);
            }
        }
        {
            size_t o0 = (size_t)(k0 + 2 * bk) * H_DIM + col0 + nc;
#pragma unroll
            for (int q = 0; q < 2; q++) {
                float4 a0 = *(const float4*)(W0 + o0 + q * 4);
                float4 b0 = *(const float4*)(W1 + o0 + q * 4);
                float4 a1 = *(const float4*)(W0 + o0 + H_DIM + q * 4);
                float4 b1 = *(const float4*)(W1 + o0 + H_DIM + q * 4);
                float4 r0 = make_float4(w.x * a0.x + w.y * b0.x, w.x * a0.y + w.y * b0.y,
                                        w.x * a0.z + w.y * b0.z, w.x * a0.w + w.y * b0.w);
                float4 r1 = make_float4(w.x * a1.x + w.y * b1.x, w.x * a1.y + w.y * b1.y,
                                        w.x * a1.z + w.y * b1.z, w.x * a1.w + w.y * b1.w);
                uint4 h, l;
                splitB4(r0, r1, h, l);
                *(uint4*)&BsH[bk * BSTRP + nc + q * 4] = h;
                *(uint4*)&BsL[bk * BSTRP + nc + q * 4] = l;
            }
        }
        __syncthreads();

        uint32_t ah[5][4], al[5][4], bh[4][2], bl[4][2];
#pragma unroll
        for (int mt = 0; mt < 5; mt++) {
            int r = (mt * 16 + gid) * ASTRP;
            ah[mt][0] = AsH[r + tig];     ah[mt][1] = AsH[r + 8 * ASTRP + tig];
            ah[mt][2] = AsH[r + tig + 4]; ah[mt][3] = AsH[r + 8 * ASTRP + tig + 4];
            al[mt][0] = AsL[r + tig];     al[mt][1] = AsL[r + 8 * ASTRP + tig];
            al[mt][2] = AsL[r + tig + 4]; al[mt][3] = AsL[r + 8 * ASTRP + tig + 4];
        }
#pragma unroll
        for (int nt = 0; nt < 4; nt++) {
            int c = wn * 32 + nt * 8 + gid;
            bh[nt][0] = BsH[tig * BSTRP + c]; bh[nt][1] = BsH[(tig + 4) * BSTRP + c];
            bl[nt][0] = BsL[tig * BSTRP + c]; bl[nt][1] = BsL[(tig + 4) * BSTRP + c];
        }
#pragma unroll
        for (int mt = 0; mt < 5; mt++)
#pragma unroll
            for (int nt = 0; nt < 4; nt++) mma16(acc[mt][nt], ah[mt], bh[nt]);
#pragma unroll
        for (int mt = 0; mt < 5; mt++)
#pragma unroll
            for (int nt = 0; nt < 4; nt++) mma16(acc[mt][nt], ah[mt], bl[nt]);
#pragma unroll
        for (int mt = 0; mt < 5; mt++)
#pragma unroll
            for (int nt = 0; nt < 4; nt++) mma16(acc[mt][nt], al[mt], bh[nt]);
        __syncthreads();
    }

#pragma unroll
    for (int mt = 0; mt < 5; mt++) {
        int t = mt * 16 + gid;
#pragma unroll
        for (int nt = 0; nt < 4; nt++) {
            int n = col0 + wn * 32 + nt * 8 + tig * 2;
            float b0 = w.x * be[e.x * H_DIM + n]     + w.y * be[e.y * H_DIM + n];
            float b1 = w.x * be[e.x * H_DIM + n + 1] + w.y * be[e.y * H_DIM + n + 1];
            if (t < S)
                *(float2*)(out + ((size_t)i * S + t) * H_DIM + n) =
                    make_float2(acc[mt][nt][0] + b0, acc[mt][nt][1] + b1);
            if (t + 8 < S)
                *(float2*)(out + ((size_t)i * S + t + 8) * H_DIM + n) =
                    make_float2(acc[mt][nt][2] + b0, acc[mt][nt][3] + b1);
        }
    }
}

// ------ router weight folding + projection-weight pre-split (one kernel) ----
__global__ void combine_w_kernel(const float* __restrict__ Wt, const float* __restrict__ Wi,
                                 const float* __restrict__ Wr,
                                 float* __restrict__ WcT, float* __restrict__ WcI,
                                 uint32_t* __restrict__ Wh, uint32_t* __restrict__ Wl)
{
    int idx = blockIdx.x * blockDim.x + threadIdx.x;
    if (idx < D_IN * N_EXP) {
        int k = idx >> 3, e = idx & 7;
        float st = 0.f, si = 0.f;
        for (int h = 0; h < H_DIM; h++) {
            float wr = Wr[h * N_EXP + e];
            st += Wt[(size_t)k * H_DIM + h] * wr;
            si += Wi[(size_t)k * H_DIM + h] * wr;
        }
        WcT[idx] = st;
        WcI[idx] = si;
    }
    if (idx < 2 * WSP_SZ) {
        int which = idx / WSP_SZ;
        int rem = idx - which * WSP_SZ;
        int p = rem / H_DIM, n = rem - (rem / H_DIM) * H_DIM;
        const float* W = which ? Wi : Wt;
        float a = W[(size_t)(2 * p) * H_DIM + n];
        float b = W[(size_t)(2 * p + 1) * H_DIM + n];
        uint32_t h, l;
        split_bf16x2(a, b, h, l);
        Wh[idx] = h;
        Wl[idx] = l;
    }
}

__global__ void bterm_kernel(const float* __restrict__ bt, const float* __restrict__ bi,
                             const float* __restrict__ Wr, const float* __restrict__ br,
                             float* __restrict__ bterm)
{
    int e = threadIdx.x;
    if (e < N_EXP) {
        float sA = 0.f, sB = 0.f;
        for (int h = 0; h < H_DIM; h++) {
            float wr = Wr[h * N_EXP + e];
            sA += (bi[h] + 64.f * bt[h]) * wr;
            sB += (bt[h] + 49.f * bi[h]) * wr;
        }
        bterm[e]         = sA / 65.f + br[e];
        bterm[N_EXP + e] = sB / 50.f + br[e];
    }
}

// -------- router: stage1 bandwidth token-sum (float4), stage2 logits -------
__global__ __launch_bounds__(256) void router2_kernel(
    const float* __restrict__ cls, const float* __restrict__ tok, int Sm1,
    const float* __restrict__ WcCls, const float* __restrict__ WcTok,
    const float* __restrict__ bt,
    int2* __restrict__ eidx, float2* __restrict__ ew)
{
    const int i = blockIdx.x, tid = threadIdx.x;
    __shared__ float sumtok[D_IN];
    __shared__ float red[8][N_EXP];
    __shared__ float logits[N_EXP];

    if (tid < 192) {
        const float4* tp = (const float4*)(tok + (size_t)i * Sm1 * D_IN) + tid;
        float4 s0 = make_float4(0.f, 0.f, 0.f, 0.f), s1 = s0, s2 = s0, s3 = s0;
        int t = 0;
        for (; t + 4 <= Sm1; t += 4) {
            float4 a = tp[(size_t)(t + 0) * 192];
            float4 b = tp[(size_t)(t + 1) * 192];
            float4 c = tp[(size_t)(t + 2) * 192];
            float4 d = tp[(size_t)(t + 3) * 192];
            s0.x += a.x; s0.y += a.y; s0.z += a.z; s0.w += a.w;
            s1.x += b.x; s1.y += b.y; s1.z += b.z; s1.w += b.w;
            s2.x += c.x; s2.y += c.y; s2.z += c.z; s2.w += c.w;
            s3.x += d.x; s3.y += d.y; s3.z += d.z; s3.w += d.w;
        }
        for (; t < Sm1; t++) {
            float4 a = tp[(size_t)t * 192];
            s0.x += a.x; s0.y += a.y; s0.z += a.z; s0.w += a.w;
        }
        float4 s = make_float4(s0.x + s1.x + s2.x + s3.x, s0.y + s1.y + s2.y + s3.y,
                               s0.z + s1.z + s2.z + s3.z, s0.w + s1.w + s2.w + s3.w);
        *(float4*)&sumtok[tid * 4] = s;
    }
    __syncthreads();

    const int warp = tid >> 5, lane = tid & 31;
    {
        float part[N_EXP];
#pragma unroll
        for (int e = 0; e < N_EXP; e++) part[e] = 0.f;
        for (int c = tid; c < D_IN; c += 256) {
            float cl = cls[(size_t)i * D_IN + c];
            float s = sumtok[c];
#pragma unroll
            for (int e = 0; e < N_EXP; e++)
                part[e] += cl * WcCls[c * N_EXP + e] + s * WcTok[c * N_EXP + e];
        }
#pragma unroll
        for (int o = 16; o; o >>= 1)
#pragma unroll
            for (int e = 0; e < N_EXP; e++)
                part[e] += __shfl_down_sync(0xffffffffu, part[e], o);
        if (lane == 0)
#pragma unroll
            for (int e = 0; e < N_EXP; e++) red[warp][e] = part[e];
    }
    __syncthreads();
    if (tid < N_EXP) {
        float l = 0.f;
        for (int wq = 0; wq < 8; wq++) l += red[wq][tid];
        logits[tid] = l / (float)(Sm1 + 1) + bt[tid];
    }
    __syncthreads();
    if (tid == 0) {
        int b0 = 0;
        for (int e = 1; e < N_EXP; e++)
            if (logits[e] > logits[b0]) b0 = e;
        int b1 = (b0 == 0) ? 1 : 0;
        for (int e = 0; e < N_EXP; e++)
            if (e != b0 && logits[e] > logits[b1]) b1 = e;
        float e1v = expf(logits[b1] - logits[b0]);
        float inv = 1.0f / (1.0f + e1v);
        eidx[i] = make_int2(b0, b1);
        ew[i] = make_float2(inv, e1v * inv);
    }
}

// ------------- cross attention: tokens resident in dynamic smem -------------
__global__ __launch_bounds__(256) void cross_kernel(
    const float* __restrict__ moe_out, int S, float* __restrict__ ctx)
{
    extern __shared__ float tokbuf[];           // S * H_DIM floats
    __shared__ float prob[64];
    const int i = blockIdx.x;
    const int tid = threadIdx.x;
    const float* base = moe_out + (size_t)i * S * H_DIM;

    // single pass over DRAM: load whole block into smem
    {
        const float4* src = (const float4*)base;
        float4* dst = (float4*)tokbuf;
        const int n4 = S * (H_DIM / 4);
        for (int idx = tid; idx < n4; idx += 256) dst[idx] = src[idx];
    }
    __syncthreads();

    const int nt = S - 1;
    const int warp = tid >> 5, lane = tid & 31;
    for (int s = warp; s < nt; s += 8) {
        const float4* tr = (const float4*)(tokbuf + (s + 1) * H_DIM);
        const float4* cl = (const float4*)tokbuf;
        float p = 0.f;
#pragma unroll
        for (int q = 0; q < 4; q++) {
            float4 a = cl[lane + 32 * q];
            float4 b = tr[lane + 32 * q];
            p += a.x * b.x + a.y * b.y + a.z * b.z + a.w * b.w;
        }
#pragma unroll
        for (int o = 16; o; o >>= 1) p += __shfl_down_sync(0xffffffffu, p, o);
        if (lane == 0) prob[s] = p;
    }
    __syncthreads();

    if (tid == 0) {
        float mx = -1e30f;
        for (int s = 0; s < nt; s++) mx = fmaxf(mx, prob[s]);
        float sum = 0.f;
        for (int s = 0; s < nt; s++) { float e = expf(prob[s] - mx); prob[s] = e; sum += e; }
        float inv = 1.0f / sum;
        for (int s = 0; s < nt; s++) prob[s] *= inv;
    }
    __syncthreads();

    float2 acc = make_float2(0.f, 0.f);
    const float2* b2 = (const float2*)(tokbuf + H_DIM) + tid;
#pragma unroll 4
    for (int s = 0; s < nt; s++) {
        float2 v = b2[(size_t)s * (H_DIM / 2)];
        float pw = prob[s];
        acc.x += pw * v.x; acc.y += pw * v.y;
    }
    ((float2*)(ctx + (size_t)i * H_DIM))[tid] = acc;
}

// --------------------------- gate + residual + LN ---------------------------
__global__ __launch_bounds__(256) void gate_ln_kernel(
    const float* __restrict__ ori, const float* __restrict__ ctx,
    const float* __restrict__ Wg, const float* __restrict__ bg,
    const float* __restrict__ ls, const float* __restrict__ lb,
    float* __restrict__ out, int gate_from_ctx)
{
    const int i = blockIdx.x;
    __shared__ float v[H_DIM];
    __shared__ float red[256];
    const int tid = threadIdx.x;
    const float* orow = ori + (size_t)i * H_DIM;
    const float* crow = ctx + (size_t)i * H_DIM;

    float p = 0.f;
    for (int c = tid; c < H_DIM; c += 256) {
        float gs = gate_from_ctx ? crow[c] : orow[c];
        p += gs * Wg[c];
    }
    red[tid] = p; __syncthreads();
    for (int o = 128; o; o >>= 1) { if (tid < o) red[tid] += red[tid + o]; __syncthreads(); }
    float gate = tanhf(red[0] + bg[0]);
    __syncthreads();

    float sum = 0.f;
    for (int c = tid; c < H_DIM; c += 256) {
        float val = orow[c] * gate + crow[c];
        v[c] = val; sum += val;
    }
    red[tid] = sum; __syncthreads();
    for (int o = 128; o; o >>= 1) { if (tid < o) red[tid] += red[tid + o]; __syncthreads(); }
    float mean = red[0] / (float)H_DIM;
    __syncthreads();

    float var = 0.f;
    for (int c = tid; c < H_DIM; c += 256) { float d = v[c] - mean; var += d * d; }
    red[tid] = var; __syncthreads();
    for (int o = 128; o; o >>= 1) { if (tid < o) red[tid] += red[tid + o]; __syncthreads(); }
    float rstd = rsqrtf(red[0] / (float)H_DIM + 1e-5f);

    for (int c = tid; c < H_DIM; c += 256)
        out[(size_t)i * H_DIM + c] = (v[c] - mean) * rstd * ls[c] + lb[c];
}

// -------------------------------- final score -------------------------------
__global__ __launch_bounds__(256) void score_kernel(
    const float* __restrict__ mti, const float* __restrict__ eti,
    const float* __restrict__ mit, const float* __restrict__ eit,
    float* __restrict__ out)
{
    __shared__ float As[8][64];
    __shared__ float Bs[8][64];
    const int n0 = blockIdx.x * 64;
    const int b0 = blockIdx.y * 64;
    const int tid = threadIdx.x;
    const int tx = tid & 15, ty = tid >> 4;
    const int lrow = tid >> 2, lcol = (tid & 3) * 2;

    float acc[4][4];
#pragma unroll
    for (int q = 0; q < 4; q++)
#pragma unroll
        for (int r = 0; r < 4; r++) acc[q][r] = 0.f;

#pragma unroll
    for (int pass = 0; pass < 2; pass++) {
        const float* A = pass ? mit : mti;
        const float* B = pass ? eit : eti;
        for (int k0 = 0; k0 < H_DIM; k0 += 8) {
            float2 av = *(const float2*)(A + (size_t)(b0 + lrow) * H_DIM + k0 + lcol);
            As[lcol][lrow] = av.x; As[lcol + 1][lrow] = av.y;
            float2 bv = *(const float2*)(B + (size_t)(n0 + lrow) * H_DIM + k0 + lcol);
            Bs[lcol][lrow] = bv.x; Bs[lcol + 1][lrow] = bv.y;
            __syncthreads();
#pragma unroll
            for (int k = 0; k < 8; k++) {
                float a[4], b[4];
#pragma unroll
                for (int q = 0; q < 4; q++) a[q] = As[k][ty * 4 + q];
#pragma unroll
                for (int q = 0; q < 4; q++) b[q] = Bs[k][tx * 4 + q];
#pragma unroll
                for (int q = 0; q < 4; q++)
#pragma unroll
                    for (int r = 0; r < 4; r++) acc[q][r] += a[q] * b[r];
            }
            __syncthreads();
        }
    }
#pragma unroll
    for (int q = 0; q < 4; q++)
#pragma unroll
        for (int r = 0; r < 4; r++)
            out[(size_t)(b0 + ty * 4 + q) * N_ENT + (n0 + tx * 4 + r)] = 0.5f * acc[q][r];
}

// ---------------------------------- launch ----------------------------------
extern "C" void kernel_launch(void* const* d_in, const int* in_sizes, int n_in,
                              void* d_out, int out_size)
{
    const float* etc_in = (const float*)d_in[0];
    const float* ett_in = (const float*)d_in[1];
    const float* mtc_in = (const float*)d_in[2];
    const float* mtt_in = (const float*)d_in[3];
    const float* eic_in = (const float*)d_in[4];
    const float* eit_in = (const float*)d_in[5];
    const float* mic_in = (const float*)d_in[6];
    const float* mit_in = (const float*)d_in[7];
    const float* W_text = (const float*)d_in[8];
    const float* b_text = (const float*)d_in[9];
    const float* W_img  = (const float*)d_in[10];
    const float* b_img  = (const float*)d_in[11];
    const float* W_gate = (const float*)d_in[12];
    const float* b_gate = (const float*)d_in[13];
    const float* ln_s   = (const float*)d_in[14];
    const float* ln_b   = (const float*)d_in[15];
    const float* W_rout = (const float*)d_in[16];
    const float* b_rout = (const float*)d_in[17];
    const float* W_exp  = (const float*)d_in[18];
    const float* b_exp  = (const float*)d_in[19];
    float* out = (float*)d_out;

    float *p_etc, *p_eic, *p_mtc, *p_mic, *p_ett, *p_eit, *p_mtt, *p_mit;
    float *p_etim, *p_mtim, *p_eitm, *p_mitm;
    float *p_ctx0, *p_ctx1, *p_ctx2, *p_ctx3;
    float *p_feti, *p_fmti, *p_feit, *p_fmit;
    float *p_wct, *p_wci, *p_bt;
    uint32_t *p_wh, *p_wl;
    int2* p_eidx; float2* p_ew;
    cudaGetSymbolAddress((void**)&p_etc, g_etc);
    cudaGetSymbolAddress((void**)&p_eic, g_eic);
    cudaGetSymbolAddress((void**)&p_mtc, g_mtc);
    cudaGetSymbolAddress((void**)&p_mic, g_mic);
    cudaGetSymbolAddress((void**)&p_ett, g_ett);
    cudaGetSymbolAddress((void**)&p_eit, g_eit);
    cudaGetSymbolAddress((void**)&p_mtt, g_mtt);
    cudaGetSymbolAddress((void**)&p_mit, g_mit);
    cudaGetSymbolAddress((void**)&p_etim, g_eti_m);
    cudaGetSymbolAddress((void**)&p_mtim, g_mti_m);
    cudaGetSymbolAddress((void**)&p_eitm, g_eit_m);
    cudaGetSymbolAddress((void**)&p_mitm, g_mit_m);
    cudaGetSymbolAddress((void**)&p_ctx0, g_ctx0);
    cudaGetSymbolAddress((void**)&p_ctx1, g_ctx1);
    cudaGetSymbolAddress((void**)&p_ctx2, g_ctx2);
    cudaGetSymbolAddress((void**)&p_ctx3, g_ctx3);
    cudaGetSymbolAddress((void**)&p_feti, g_fe_ti);
    cudaGetSymbolAddress((void**)&p_fmti, g_fm_ti);
    cudaGetSymbolAddress((void**)&p_feit, g_fe_it);
    cudaGetSymbolAddress((void**)&p_fmit, g_fm_it);
    cudaGetSymbolAddress((void**)&p_wct, g_wc_text);
    cudaGetSymbolAddress((void**)&p_wci, g_wc_img);
    cudaGetSymbolAddress((void**)&p_bt, g_bterm);
    cudaGetSymbolAddress((void**)&p_wh, g_wsp_h);
    cudaGetSymbolAddress((void**)&p_wl, g_wsp_l);
    cudaGetSymbolAddress((void**)&p_eidx, g_eidx);
    cudaGetSymbolAddress((void**)&p_ew,   g_ew);

    const int CROSS_SMEM = 65 * H_DIM * 4;   // max S
    cudaFuncSetAttribute(cross_kernel, cudaFuncAttributeMaxDynamicSharedMemorySize, CROSS_SMEM);

    dim3 blk(256);
    dim3 blkg(128);

    // 1: prep (router fold + proj weight pre-split)
    combine_w_kernel<<<(2 * WSP_SZ + 255) / 256, blk>>>(W_text, W_img, W_rout,
                                                        p_wct, p_wci, p_wh, p_wl);
    // 2: bias terms
    bterm_kernel<<<1, 32>>>(b_text, b_img, W_rout, b_rout, p_bt);

    // 3: first big router
    router2_kernel<<<N_ENT, blk>>>(eic_in, ett_in, T_TOK, p_wci, p_wct, p_bt,
                                   p_eidx + 0 * N_ENT, p_ew + 0 * N_ENT);

    // 4: big ett projection — positioned for ncu capture
    proj_tc<<<dim3(4, N_ENT * T_TOK / 128), blkg>>>(ett_in, p_wh, p_wl, b_text, p_ett, N_ENT * T_TOK);

    // remaining routers
    router2_kernel<<<BATCH, blk>>>(mic_in, mtt_in, T_TOK, p_wci, p_wct, p_bt,
                                   p_eidx + 1 * N_ENT, p_ew + 1 * N_ENT);
    router2_kernel<<<N_ENT, blk>>>(etc_in, eit_in, P_TOK, p_wct, p_wci, p_bt + N_EXP,
                                   p_eidx + 2 * N_ENT, p_ew + 2 * N_ENT);
    router2_kernel<<<BATCH, blk>>>(mtc_in, mit_in, P_TOK, p_wct, p_wci, p_bt + N_EXP,
                                   p_eidx + 3 * N_ENT, p_ew + 3 * N_ENT);

    // remaining projections (text -> offset 0, img -> offset WSP_SZ)
    proj_tc<<<dim3(4, N_ENT / 128), blkg>>>(etc_in, p_wh, p_wl, b_text, p_etc, N_ENT);
    proj_tc<<<dim3(4, BATCH / 128), blkg>>>(mtc_in, p_wh, p_wl, b_text, p_mtc, BATCH);
    proj_tc<<<dim3(4, BATCH * T_TOK / 128), blkg>>>(mtt_in, p_wh, p_wl, b_text, p_mtt, BATCH * T_TOK);
    proj_tc<<<dim3(4, N_ENT / 128), blkg>>>(eic_in, p_wh + WSP_SZ, p_wl + WSP_SZ, b_img, p_eic, N_ENT);
    proj_tc<<<dim3(4, N_ENT * P_TOK / 128), blkg>>>(eit_in, p_wh + WSP_SZ, p_wl + WSP_SZ, b_img, p_eit, N_ENT * P_TOK);
    proj_tc<<<dim3(4, BATCH / 128), blkg>>>(mic_in, p_wh + WSP_SZ, p_wl + WSP_SZ, b_img, p_mic, BATCH);
    proj_tc<<<dim3(4, BATCH * P_TOK / 128), blkg>>>(mit_in, p_wh + WSP_SZ, p_wl + WSP_SZ, b_img, p_mit, BATCH * P_TOK);

    // MoE GEMMs (combined expert pair, bf16x3)
    moe2_tc<<<dim3(2, 1, N_ENT), blkg>>>(p_etc, p_eit, W_exp, b_exp,
                                         p_eidx + 0 * N_ENT, p_ew + 0 * N_ENT, p_etim);
    moe2_tc<<<dim3(2, 1, BATCH), blkg>>>(p_mtc, p_mit, W_exp, b_exp,
                                         p_eidx + 1 * N_ENT, p_ew + 1 * N_ENT, p_mtim);
    moe3_tc<<<dim3(4, 1, N_ENT), blkg>>>(p_eic, p_ett, W_exp, b_exp,
                                         p_eidx + 2 * N_ENT, p_ew + 2 * N_ENT, p_eitm);
    moe3_tc<<<dim3(4, 1, BATCH), blkg>>>(p_mic, p_mtt, W_exp, b_exp,
                                         p_eidx + 3 * N_ENT, p_ew + 3 * N_ENT, p_mitm);

    // cross attention (tokens smem-resident)
    cross_kernel<<<N_ENT, blk, 50 * H_DIM * 4>>>(p_etim, 50, p_ctx0);
    cross_kernel<<<BATCH, blk, 50 * H_DIM * 4>>>(p_mtim, 50, p_ctx1);
    cross_kernel<<<N_ENT, blk, 65 * H_DIM * 4>>>(p_eitm, 65, p_ctx2);
    cross_kernel<<<BATCH, blk, 65 * H_DIM * 4>>>(p_mitm, 65, p_ctx3);

    // gate + residual + LN
    gate_ln_kernel<<<N_ENT, blk>>>(p_etc, p_ctx0, W_gate, b_gate, ln_s, ln_b, p_feti, 1);
    gate_ln_kernel<<<BATCH, blk>>>(p_mtc, p_ctx1, W_gate, b_gate, ln_s, ln_b, p_fmti, 0);
    gate_ln_kernel<<<N_ENT, blk>>>(p_eic, p_ctx2, W_gate, b_gate, ln_s, ln_b, p_feit, 1);
    gate_ln_kernel<<<BATCH, blk>>>(p_mic, p_ctx3, W_gate, b_gate, ln_s, ln_b, p_fmit, 0);

    // final score
    score_kernel<<<dim3(N_ENT / 64, BATCH / 64), blk>>>(p_fmti, p_feti, p_fmit, p_feit, out);
}